// round 4
// baseline (speedup 1.0000x reference)
#include <cuda_runtime.h>

#define NS   512
#define TN   20000
#define ND   2000
#define DTC  30.0f
#define NLEV 10   // scan window 2^10 = 1024 ; ||M^1024|| < 2e-6 worst-case

// ---------------- static scratch (no allocations allowed) ----------------
__device__ float d_Ea[(size_t)TN * NS];     // 41 MB ping buffer (pairs with d_out)
__device__ float d_Lt[NS * NS];             // (dt*A)^T
__device__ float d_G1[NS * NS];
__device__ float d_G2[NS * NS];
__device__ float d_W[NLEV][NS * NS];        // W_k = (M^{2^k})^T
__device__ float d_vec[13 * NS];            // g,h,Lg,L2g,L3g,Lh,L2h,L3h,w1..w4,v

// ---------------- small helpers ----------------
__global__ void k_tpose(const float* __restrict__ A, float* __restrict__ Lt) {
    int idx = blockIdx.x * blockDim.x + threadIdx.x;
    if (idx < NS * NS) {
        int i = idx >> 9, j = idx & 511;
        Lt[idx] = DTC * A[j * NS + i];
    }
}

__global__ void k_gh(const float* __restrict__ B, const float* __restrict__ Q,
                     float* __restrict__ g, float* __restrict__ h) {
    int i = blockIdx.x * blockDim.x + threadIdx.x;
    if (i < NS) {
        g[i] = B[i * 9];
        float s = 0.f;
#pragma unroll
        for (int m = 0; m < 8; m++) s += B[i * 9 + 1 + m] * Q[m];
        h[i] = s;
    }
}

// y = scale * (A @ x)   (one block per output row)
__global__ void k_matvec(const float* __restrict__ A, const float* __restrict__ x,
                         float* __restrict__ y, float scale) {
    __shared__ float red[128];
    int row = blockIdx.x;
    float s = 0.f;
    for (int j = threadIdx.x; j < NS; j += 128) s += A[row * NS + j] * x[j];
    red[threadIdx.x] = s;
    __syncthreads();
    for (int st = 64; st > 0; st >>= 1) {
        if (threadIdx.x < st) red[threadIdx.x] += red[threadIdx.x + st];
        __syncthreads();
    }
    if (threadIdx.x == 0) y[row] = scale * red[0];
}

// build w1..w4, v from g,h and their L-powers
__global__ void k_combine(float* __restrict__ vec) {
    int i = blockIdx.x * blockDim.x + threadIdx.x;
    if (i >= NS) return;
    const float G   = vec[0 * NS + i], H   = vec[1 * NS + i];
    const float LG  = vec[2 * NS + i], L2G = vec[3 * NS + i], L3G = vec[4 * NS + i];
    const float LH  = vec[5 * NS + i], L2H = vec[6 * NS + i], L3H = vec[7 * NS + i];
    const float c = DTC / 8.0f;
    vec[8  * NS + i] = c * (G + LG + (L2G + L3G) * (1.0f / 3.0f));
    vec[9  * NS + i] = c * (3.0f * G + 2.0f * LG + L2G);
    vec[10 * NS + i] = c * (3.0f * G + LG);
    vec[11 * NS + i] = c * G;
    vec[12 * NS + i] = DTC * (H + 0.5f * LH + L2H * (1.0f / 6.0f) + L3H * (1.0f / 24.0f));
}

// C = alpha*X + I
__global__ void k_axpyI(const float* __restrict__ X, float* __restrict__ C, float alpha) {
    int idx = blockIdx.x * blockDim.x + threadIdx.x;
    if (idx < NS * NS) {
        int i = idx >> 9, j = idx & 511;
        C[idx] = alpha * X[idx] + (i == j ? 1.0f : 0.0f);
    }
}

// ---------------- 512x512x512 GEMM: C = alpha*(A@B) + (addI ? I : 0) ----------------
__global__ void __launch_bounds__(256) k_gemm512(
    const float* __restrict__ A, const float* __restrict__ B, float* __restrict__ C,
    float alpha, int addI)
{
    __shared__ float As[16][68];
    __shared__ float Bs[16][68];
    const int t  = threadIdx.x;
    const int tx = t & 15, ty = t >> 4;
    const int r0 = blockIdx.y * 64, c0 = blockIdx.x * 64;

    const int arow = t >> 2,  ac4 = (t & 3)  * 4;   // A: 64 rows x 16 cols
    const int brow = t >> 4,  bc4 = (t & 15) * 4;   // B: 16 rows x 64 cols

    float acc[4][4];
#pragma unroll
    for (int m = 0; m < 4; m++)
#pragma unroll
        for (int n = 0; n < 4; n++) acc[m][n] = 0.f;

    for (int it = 0; it < 32; ++it) {
        const int k0 = it * 16;
        float4 av = *(const float4*)(A + (size_t)(r0 + arow) * NS + k0 + ac4);
        float4 bv = *(const float4*)(B + (size_t)(k0 + brow) * NS + c0 + bc4);
        As[ac4 + 0][arow] = av.x; As[ac4 + 1][arow] = av.y;
        As[ac4 + 2][arow] = av.z; As[ac4 + 3][arow] = av.w;
        *(float4*)&Bs[brow][bc4] = bv;
        __syncthreads();
#pragma unroll
        for (int kk = 0; kk < 16; ++kk) {
            float a[4], b[4];
            *(float4*)a = *(const float4*)&As[kk][ty * 4];
            *(float4*)b = *(const float4*)&Bs[kk][tx * 4];
#pragma unroll
            for (int m = 0; m < 4; m++)
#pragma unroll
                for (int n = 0; n < 4; n++) acc[m][n] += a[m] * b[n];
        }
        __syncthreads();
    }
#pragma unroll
    for (int m = 0; m < 4; m++) {
        int row = r0 + ty * 4 + m;
#pragma unroll
        for (int n = 0; n < 4; n++) {
            int col = c0 + tx * 4 + n;
            C[(size_t)row * NS + col] =
                alpha * acc[m][n] + ((addI && row == col) ? 1.0f : 0.0f);
        }
    }
}

// ---------------- E0 = [iv ; d_0 ; d_1 ; ... ; d_{T-2}] ----------------
__device__ __forceinline__ float dev_interp(const float* __restrict__ Tt,
                                            const float* __restrict__ Tv, float tq) {
    if (tq <= Tt[0])      return Tv[0];
    if (tq >= Tt[ND - 1]) return Tv[ND - 1];
    int lo = 0, hi = ND - 1;
    while (hi - lo > 1) {
        int mid = (lo + hi) >> 1;
        if (Tt[mid] <= tq) lo = mid; else hi = mid;
    }
    float x0 = Tt[lo], x1 = Tt[lo + 1];
    return Tv[lo] + (tq - x0) * (Tv[lo + 1] - Tv[lo]) / (x1 - x0);
}

__global__ void k_buildE0(const float* __restrict__ Tt, const float* __restrict__ Tv,
                          const float* __restrict__ iv, const float* __restrict__ vec,
                          float* __restrict__ E0)
{
    const int n = blockIdx.x;
    const int t = threadIdx.x;  // 128
    if (n == 0) {
        for (int i = t; i < NS; i += 128) E0[i] = iv[i];
        return;
    }
    __shared__ float s[4];
    if (t < 4) {
        float tq = (float)(n - 1) * DTC + (float)t * 10.0f;  // t, t+dt/3, t+2dt/3, t+dt
        s[t] = dev_interp(Tt, Tv, tq);
    }
    __syncthreads();
    const float s1 = s[0], s2 = s[1], s3 = s[2], s4 = s[3];
    const float* w1 = vec + 8  * NS;
    const float* w2 = vec + 9  * NS;
    const float* w3 = vec + 10 * NS;
    const float* w4 = vec + 11 * NS;
    const float* vv = vec + 12 * NS;
    float* row = E0 + (size_t)n * NS;
    for (int i = t; i < NS; i += 128)
        row[i] = s1 * w1[i] + s2 * w2[i] + s3 * w3[i] + s4 * w4[i] + vv[i];
}

// ---------------- scan level: Eout[n] = Ein[n] + Ein[n-off] @ W  (f32x2 FMA) ----------------
__global__ void __launch_bounds__(256, 2) k_scan(
    const float* __restrict__ Ein, const float* __restrict__ W,
    float* __restrict__ Eout, int off)
{
    __shared__ float As[16][132];   // transposed A tile [k][row], +4 pad
    __shared__ float Bs[16][132];   // B tile [k][col], +4 pad

    const int t  = threadIdx.x;
    const int tx = t & 15;
    const int ty = t >> 4;
    const int r0 = blockIdx.y * 128;
    const int c0 = blockIdx.x * 128;

    // A (shifted E): 128 rows x 16 cols -> 512 float4, 2 per thread
    const int  arow = t >> 2;           // 0..63
    const int  ac4  = (t & 3) * 4;      // 0,4,8,12
    const long gr0  = (long)r0 + arow - off;
    const long gr1  = gr0 + 64;
    const bool v0 = (gr0 >= 0) && (gr0 < TN);
    const bool v1 = (gr1 >= 0) && (gr1 < TN);

    // B (W): 16 rows x 128 cols -> 512 float4, 2 per thread
    const int brow = t >> 5;            // 0..7
    const int bc4  = (t & 31) * 4;      // 0..124

    unsigned long long acc[8][4];
#pragma unroll
    for (int m = 0; m < 8; m++)
#pragma unroll
        for (int p = 0; p < 4; p++) acc[m][p] = 0ull;

    const float4 f4z = make_float4(0.f, 0.f, 0.f, 0.f);
    float4 a0, a1, b0, b1;
    a0 = v0 ? *(const float4*)(Ein + gr0 * NS + ac4) : f4z;
    a1 = v1 ? *(const float4*)(Ein + gr1 * NS + ac4) : f4z;
    b0 = *(const float4*)(W + (size_t)brow * NS + c0 + bc4);
    b1 = *(const float4*)(W + (size_t)(brow + 8) * NS + c0 + bc4);

    for (int it = 0; it < 32; ++it) {
        As[ac4 + 0][arow]      = a0.x; As[ac4 + 1][arow]      = a0.y;
        As[ac4 + 2][arow]      = a0.z; As[ac4 + 3][arow]      = a0.w;
        As[ac4 + 0][arow + 64] = a1.x; As[ac4 + 1][arow + 64] = a1.y;
        As[ac4 + 2][arow + 64] = a1.z; As[ac4 + 3][arow + 64] = a1.w;
        *(float4*)&Bs[brow][bc4]     = b0;
        *(float4*)&Bs[brow + 8][bc4] = b1;
        __syncthreads();

        if (it < 31) {  // stage next tile while computing (latency overlap)
            const int k0 = (it + 1) * 16;
            a0 = v0 ? *(const float4*)(Ein + gr0 * NS + k0 + ac4) : f4z;
            a1 = v1 ? *(const float4*)(Ein + gr1 * NS + k0 + ac4) : f4z;
            b0 = *(const float4*)(W + (size_t)(k0 + brow) * NS + c0 + bc4);
            b1 = *(const float4*)(W + (size_t)(k0 + brow + 8) * NS + c0 + bc4);
        }

#pragma unroll
        for (int kk = 0; kk < 16; ++kk) {
            float a[8];
            *(float4*)&a[0] = *(const float4*)&As[kk][ty * 8];
            *(float4*)&a[4] = *(const float4*)&As[kk][ty * 8 + 4];
            ulonglong2 bp0 = *(const ulonglong2*)&Bs[kk][tx * 8];
            ulonglong2 bp1 = *(const ulonglong2*)&Bs[kk][tx * 8 + 4];
            unsigned long long bv[4] = {bp0.x, bp0.y, bp1.x, bp1.y};
#pragma unroll
            for (int m = 0; m < 8; m++) {
                unsigned long long av;
                asm("mov.b64 %0, {%1, %1};" : "=l"(av) : "f"(a[m]));
#pragma unroll
                for (int p = 0; p < 4; p++)
                    asm("fma.rn.f32x2 %0, %1, %2, %0;"
                        : "+l"(acc[m][p]) : "l"(av), "l"(bv[p]));
            }
        }
        __syncthreads();
    }

    // epilogue: add same-index E row, store
#pragma unroll
    for (int m = 0; m < 8; m++) {
        const long r = (long)r0 + ty * 8 + m;
        if (r < TN) {
            const float* erow = Ein + r * NS + c0 + tx * 8;
            float4 e0 = *(const float4*)erow;
            float4 e1 = *(const float4*)(erow + 4);
            float c[8];
#pragma unroll
            for (int p = 0; p < 4; p++)
                asm("mov.b64 {%0, %1}, %2;"
                    : "=f"(c[2 * p]), "=f"(c[2 * p + 1]) : "l"(acc[m][p]));
            float4 o0 = make_float4(c[0] + e0.x, c[1] + e0.y, c[2] + e0.z, c[3] + e0.w);
            float4 o1 = make_float4(c[4] + e1.x, c[5] + e1.y, c[6] + e1.z, c[7] + e1.w);
            float* orow = Eout + r * NS + c0 + tx * 8;
            *(float4*)orow       = o0;
            *(float4*)(orow + 4) = o1;
        }
    }
}

// ---------------- host orchestration (graph-capturable, alloc-free) ----------------
extern "C" void kernel_launch(void* const* d_in, const int* in_sizes, int n_in,
                              void* d_out, int out_size) {
    const float* A  = (const float*)d_in[0];   // [512,512]
    const float* Bm = (const float*)d_in[1];   // [512,9]
    const float* Q  = (const float*)d_in[2];   // [8]
    const float* Tt = (const float*)d_in[3];   // [2000]
    const float* Tv = (const float*)d_in[4];   // [2000]
    const float* iv = (const float*)d_in[5];   // [512]
    // d_in[6] = t_eval (implied by n*DT, unused)
    float* out = (float*)d_out;                // [20000,512]

    float *Ea, *Lt, *G1, *G2, *Wb, *vec;
    cudaGetSymbolAddress((void**)&Ea,  d_Ea);
    cudaGetSymbolAddress((void**)&Lt,  d_Lt);
    cudaGetSymbolAddress((void**)&G1,  d_G1);
    cudaGetSymbolAddress((void**)&G2,  d_G2);
    cudaGetSymbolAddress((void**)&Wb,  d_W);
    cudaGetSymbolAddress((void**)&vec, d_vec);

    // Lt = (dt*A)^T
    k_tpose<<<1024, 256>>>(A, Lt);

    // g = B[:,0], h = B[:,1:] @ Q ; L-power chains
    k_gh<<<2, 256>>>(Bm, Q, vec + 0 * NS, vec + 1 * NS);
    k_matvec<<<512, 128>>>(A, vec + 0 * NS, vec + 2 * NS, DTC);  // Lg
    k_matvec<<<512, 128>>>(A, vec + 2 * NS, vec + 3 * NS, DTC);  // L2g
    k_matvec<<<512, 128>>>(A, vec + 3 * NS, vec + 4 * NS, DTC);  // L3g
    k_matvec<<<512, 128>>>(A, vec + 1 * NS, vec + 5 * NS, DTC);  // Lh
    k_matvec<<<512, 128>>>(A, vec + 5 * NS, vec + 6 * NS, DTC);  // L2h
    k_matvec<<<512, 128>>>(A, vec + 6 * NS, vec + 7 * NS, DTC);  // L3h
    k_combine<<<2, 256>>>(vec);                                   // w1..w4, v

    // W0 = M^T = I + Lt(I + Lt/2 (I + Lt/3 (I + Lt/4)))  (Horner)
    dim3 g8(8, 8);
    k_axpyI<<<1024, 256>>>(Lt, G1, 0.25f);
    k_gemm512<<<g8, 256>>>(Lt, G1, G2, 1.0f / 3.0f, 1);
    k_gemm512<<<g8, 256>>>(Lt, G2, G1, 0.5f, 1);
    k_gemm512<<<g8, 256>>>(Lt, G1, Wb, 1.0f, 1);

    // W_{k+1} = W_k @ W_k   (= (M^{2^{k+1}})^T)
    for (int k = 0; k < NLEV - 1; ++k)
        k_gemm512<<<g8, 256>>>(Wb + (size_t)k * NS * NS, Wb + (size_t)k * NS * NS,
                               Wb + (size_t)(k + 1) * NS * NS, 1.0f, 0);

    // E0 rows: [iv, d_0, ..., d_{T-2}]  (built directly into d_out)
    k_buildE0<<<TN, 128>>>(Tt, Tv, iv, vec, out);

    // Hillis-Steele scan of x_{n} = M x_{n-1} + d_{n-1}; ping-pong out <-> Ea.
    // NLEV=10 levels end with the result in `out`.
    float* src = out;
    float* dst = Ea;
    dim3 gs(4, (TN + 127) / 128);
    for (int k = 0; k < NLEV; ++k) {
        k_scan<<<gs, 256>>>(src, Wb + (size_t)k * NS * NS, dst, 1 << k);
        float* tmp = src; src = dst; dst = tmp;
    }
    // result now in `out`
}

// round 5
// speedup vs baseline: 1.2671x; 1.2671x over previous
#include <cuda_runtime.h>

#define NS   512
#define TN   20000
#define ND   2000
#define DTC  30.0f
#define NLEV 8    // scan window 2^8 = 256 ; ||M^256|| <= e^{-13.8} ~ 1e-6 (log-norm bound)

// ---------------- static scratch (no allocations allowed) ----------------
__device__ float d_Ea[(size_t)TN * NS];     // 41 MB ping buffer (pairs with d_out)
__device__ float d_Lt[NS * NS];             // (dt*A)^T
__device__ float d_G1[NS * NS];
__device__ float d_G2[NS * NS];
__device__ float d_W[NLEV][NS * NS];        // W_k = (M^{2^k})^T
__device__ float d_vec[13 * NS];            // g,h,Lg,L2g,L3g,Lh,L2h,L3h,w1..w4,v

// ---------------- small helpers ----------------
__global__ void k_tpose(const float* __restrict__ A, float* __restrict__ Lt) {
    int idx = blockIdx.x * blockDim.x + threadIdx.x;
    if (idx < NS * NS) {
        int i = idx >> 9, j = idx & 511;
        Lt[idx] = DTC * A[j * NS + i];
    }
}

__global__ void k_gh(const float* __restrict__ B, const float* __restrict__ Q,
                     float* __restrict__ g, float* __restrict__ h) {
    int i = blockIdx.x * blockDim.x + threadIdx.x;
    if (i < NS) {
        g[i] = B[i * 9];
        float s = 0.f;
#pragma unroll
        for (int m = 0; m < 8; m++) s += B[i * 9 + 1 + m] * Q[m];
        h[i] = s;
    }
}

// y1 = scale*(A@x1), y2 = scale*(A@x2)   (one block per output row, paired)
__global__ void k_matvec2(const float* __restrict__ A,
                          const float* __restrict__ x1, const float* __restrict__ x2,
                          float* __restrict__ y1, float* __restrict__ y2, float scale) {
    __shared__ float red1[128], red2[128];
    int row = blockIdx.x;
    float s1 = 0.f, s2 = 0.f;
    for (int j = threadIdx.x; j < NS; j += 128) {
        float a = A[row * NS + j];
        s1 += a * x1[j];
        s2 += a * x2[j];
    }
    red1[threadIdx.x] = s1; red2[threadIdx.x] = s2;
    __syncthreads();
    for (int st = 64; st > 0; st >>= 1) {
        if (threadIdx.x < st) {
            red1[threadIdx.x] += red1[threadIdx.x + st];
            red2[threadIdx.x] += red2[threadIdx.x + st];
        }
        __syncthreads();
    }
    if (threadIdx.x == 0) { y1[row] = scale * red1[0]; y2[row] = scale * red2[0]; }
}

// build w1..w4, v from g,h and their L-powers
__global__ void k_combine(float* __restrict__ vec) {
    int i = blockIdx.x * blockDim.x + threadIdx.x;
    if (i >= NS) return;
    const float G   = vec[0 * NS + i], H   = vec[1 * NS + i];
    const float LG  = vec[2 * NS + i], L2G = vec[3 * NS + i], L3G = vec[4 * NS + i];
    const float LH  = vec[5 * NS + i], L2H = vec[6 * NS + i], L3H = vec[7 * NS + i];
    const float c = DTC / 8.0f;
    vec[8  * NS + i] = c * (G + LG + (L2G + L3G) * (1.0f / 3.0f));
    vec[9  * NS + i] = c * (3.0f * G + 2.0f * LG + L2G);
    vec[10 * NS + i] = c * (3.0f * G + LG);
    vec[11 * NS + i] = c * G;
    vec[12 * NS + i] = DTC * (H + 0.5f * LH + L2H * (1.0f / 6.0f) + L3H * (1.0f / 24.0f));
}

// C = alpha*X + I
__global__ void k_axpyI(const float* __restrict__ X, float* __restrict__ C, float alpha) {
    int idx = blockIdx.x * blockDim.x + threadIdx.x;
    if (idx < NS * NS) {
        int i = idx >> 9, j = idx & 511;
        C[idx] = alpha * X[idx] + (i == j ? 1.0f : 0.0f);
    }
}

// ---------------- 512^3 GEMM (latency-optimized): C = alpha*(A@B) + (addI ? I : 0)
// 32x64 tile, 128 threads, f32x2 FMA, grid (8,16) = 128 blocks.
__global__ void __launch_bounds__(128) k_gemm512(
    const float* __restrict__ A, const float* __restrict__ B, float* __restrict__ C,
    float alpha, int addI)
{
    __shared__ float As[16][36];
    __shared__ float Bs[16][68];
    const int t  = threadIdx.x;
    const int tx = t & 7, ty = t >> 3;          // outputs: rows ty*2+{0,1}, cols tx*8..
    const int r0 = blockIdx.y * 32, c0 = blockIdx.x * 64;

    const int ar = t >> 2, ac4 = (t & 3) * 4;   // A: 32 rows x 16 cols
    const int br = t >> 4, bc4 = (t & 15) * 4;  // B: 16 rows x 64 cols (2 rows/thread)

    unsigned long long acc[2][4];
#pragma unroll
    for (int m = 0; m < 2; m++)
#pragma unroll
        for (int p = 0; p < 4; p++) acc[m][p] = 0ull;

    float4 av = *(const float4*)(A + (size_t)(r0 + ar) * NS + ac4);
    float4 b0 = *(const float4*)(B + (size_t)br * NS + c0 + bc4);
    float4 b1 = *(const float4*)(B + (size_t)(br + 8) * NS + c0 + bc4);

    for (int it = 0; it < 32; ++it) {
        As[ac4 + 0][ar] = av.x; As[ac4 + 1][ar] = av.y;
        As[ac4 + 2][ar] = av.z; As[ac4 + 3][ar] = av.w;
        *(float4*)&Bs[br][bc4]     = b0;
        *(float4*)&Bs[br + 8][bc4] = b1;
        __syncthreads();
        if (it < 31) {
            const int k0 = (it + 1) * 16;
            av = *(const float4*)(A + (size_t)(r0 + ar) * NS + k0 + ac4);
            b0 = *(const float4*)(B + (size_t)(k0 + br) * NS + c0 + bc4);
            b1 = *(const float4*)(B + (size_t)(k0 + br + 8) * NS + c0 + bc4);
        }
#pragma unroll
        for (int kk = 0; kk < 16; ++kk) {
            float a0 = As[kk][ty * 2 + 0];
            float a1 = As[kk][ty * 2 + 1];
            ulonglong2 bp0 = *(const ulonglong2*)&Bs[kk][tx * 8];
            ulonglong2 bp1 = *(const ulonglong2*)&Bs[kk][tx * 8 + 4];
            unsigned long long bv[4] = {bp0.x, bp0.y, bp1.x, bp1.y};
            unsigned long long av0, av1;
            asm("mov.b64 %0, {%1, %1};" : "=l"(av0) : "f"(a0));
            asm("mov.b64 %0, {%1, %1};" : "=l"(av1) : "f"(a1));
#pragma unroll
            for (int p = 0; p < 4; p++) {
                asm("fma.rn.f32x2 %0, %1, %2, %0;" : "+l"(acc[0][p]) : "l"(av0), "l"(bv[p]));
                asm("fma.rn.f32x2 %0, %1, %2, %0;" : "+l"(acc[1][p]) : "l"(av1), "l"(bv[p]));
            }
        }
        __syncthreads();
    }
#pragma unroll
    for (int m = 0; m < 2; m++) {
        const int row = r0 + ty * 2 + m;
#pragma unroll
        for (int p = 0; p < 4; p++) {
            float lo, hi;
            asm("mov.b64 {%0, %1}, %2;" : "=f"(lo), "=f"(hi) : "l"(acc[m][p]));
            int col = c0 + tx * 8 + 2 * p;
            C[(size_t)row * NS + col]     = alpha * lo + ((addI && row == col)     ? 1.0f : 0.0f);
            C[(size_t)row * NS + col + 1] = alpha * hi + ((addI && row == col + 1) ? 1.0f : 0.0f);
        }
    }
}

// ---------------- E0 = [iv ; d_0 ; d_1 ; ... ; d_{T-2}] ----------------
__device__ __forceinline__ float dev_interp(const float* __restrict__ Tt,
                                            const float* __restrict__ Tv, float tq) {
    if (tq <= Tt[0])      return Tv[0];
    if (tq >= Tt[ND - 1]) return Tv[ND - 1];
    int lo = 0, hi = ND - 1;
    while (hi - lo > 1) {
        int mid = (lo + hi) >> 1;
        if (Tt[mid] <= tq) lo = mid; else hi = mid;
    }
    float x0 = Tt[lo], x1 = Tt[lo + 1];
    return Tv[lo] + (tq - x0) * (Tv[lo + 1] - Tv[lo]) / (x1 - x0);
}

__global__ void k_buildE0(const float* __restrict__ Tt, const float* __restrict__ Tv,
                          const float* __restrict__ iv, const float* __restrict__ vec,
                          float* __restrict__ E0)
{
    const int n = blockIdx.x;
    const int t = threadIdx.x;  // 128
    if (n == 0) {
        for (int i = t; i < NS; i += 128) E0[i] = iv[i];
        return;
    }
    __shared__ float s[4];
    if (t < 4) {
        float tq = (float)(n - 1) * DTC + (float)t * 10.0f;  // t, t+dt/3, t+2dt/3, t+dt
        s[t] = dev_interp(Tt, Tv, tq);
    }
    __syncthreads();
    const float s1 = s[0], s2 = s[1], s3 = s[2], s4 = s[3];
    const float* w1 = vec + 8  * NS;
    const float* w2 = vec + 9  * NS;
    const float* w3 = vec + 10 * NS;
    const float* w4 = vec + 11 * NS;
    const float* vv = vec + 12 * NS;
    float* row = E0 + (size_t)n * NS;
    for (int i = t; i < NS; i += 128)
        row[i] = s1 * w1[i] + s2 * w2[i] + s3 * w3[i] + s4 * w4[i] + vv[i];
}

// ---------------- scan level: Eout[n] = Ein[n] + Ein[n-off] @ W ----------------
// 128x64 tile, 128 threads, 8x8 per thread, f32x2 FMA, occupancy 4.
__global__ void __launch_bounds__(128, 4) k_scan(
    const float* __restrict__ Ein, const float* __restrict__ W,
    float* __restrict__ Eout, int off)
{
    __shared__ float As[16][132];   // transposed A tile [k][row], +4 pad
    __shared__ float Bs[16][68];    // B tile [k][col], +4 pad

    const int t  = threadIdx.x;
    const int tx = t & 7;           // 0..7  -> 8 output cols
    const int ty = t >> 3;          // 0..15 -> 8 output rows
    const int r0 = blockIdx.y * 128;
    const int c0 = blockIdx.x * 64;

    // A (shifted E): 128 rows x 16 cols. Thread loads 4 float4 (rows ar+32g).
    const int  ar  = t >> 2;        // 0..31
    const int  ac4 = (t & 3) * 4;   // 0,4,8,12
    long gr[4]; bool v[4];
#pragma unroll
    for (int g = 0; g < 4; g++) {
        gr[g] = (long)r0 + ar + 32 * g - off;
        v[g]  = (gr[g] >= 0) && (gr[g] < TN);
    }

    // B (W): 16 rows x 64 cols. Thread loads 2 float4 (k rows br, br+8).
    const int br  = t >> 4;         // 0..7
    const int bc4 = (t & 15) * 4;   // 0..60

    unsigned long long acc[8][4];
#pragma unroll
    for (int m = 0; m < 8; m++)
#pragma unroll
        for (int p = 0; p < 4; p++) acc[m][p] = 0ull;

    const float4 f4z = make_float4(0.f, 0.f, 0.f, 0.f);
    float4 av[4], b0, b1;
#pragma unroll
    for (int g = 0; g < 4; g++)
        av[g] = v[g] ? *(const float4*)(Ein + gr[g] * NS + ac4) : f4z;
    b0 = *(const float4*)(W + (size_t)br * NS + c0 + bc4);
    b1 = *(const float4*)(W + (size_t)(br + 8) * NS + c0 + bc4);

    for (int it = 0; it < 32; ++it) {
#pragma unroll
        for (int g = 0; g < 4; g++) {
            As[ac4 + 0][ar + 32 * g] = av[g].x;
            As[ac4 + 1][ar + 32 * g] = av[g].y;
            As[ac4 + 2][ar + 32 * g] = av[g].z;
            As[ac4 + 3][ar + 32 * g] = av[g].w;
        }
        *(float4*)&Bs[br][bc4]     = b0;
        *(float4*)&Bs[br + 8][bc4] = b1;
        __syncthreads();

        if (it < 31) {  // stage next tile while computing
            const int k0 = (it + 1) * 16;
#pragma unroll
            for (int g = 0; g < 4; g++)
                av[g] = v[g] ? *(const float4*)(Ein + gr[g] * NS + k0 + ac4) : f4z;
            b0 = *(const float4*)(W + (size_t)(k0 + br) * NS + c0 + bc4);
            b1 = *(const float4*)(W + (size_t)(k0 + br + 8) * NS + c0 + bc4);
        }

#pragma unroll
        for (int kk = 0; kk < 16; ++kk) {
            float a[8];
            *(float4*)&a[0] = *(const float4*)&As[kk][ty * 8];
            *(float4*)&a[4] = *(const float4*)&As[kk][ty * 8 + 4];
            ulonglong2 bp0 = *(const ulonglong2*)&Bs[kk][tx * 8];
            ulonglong2 bp1 = *(const ulonglong2*)&Bs[kk][tx * 8 + 4];
            unsigned long long bv[4] = {bp0.x, bp0.y, bp1.x, bp1.y};
#pragma unroll
            for (int m = 0; m < 8; m++) {
                unsigned long long avv;
                asm("mov.b64 %0, {%1, %1};" : "=l"(avv) : "f"(a[m]));
#pragma unroll
                for (int p = 0; p < 4; p++)
                    asm("fma.rn.f32x2 %0, %1, %2, %0;"
                        : "+l"(acc[m][p]) : "l"(avv), "l"(bv[p]));
            }
        }
        __syncthreads();
    }

    // epilogue: add same-index E row, store
#pragma unroll
    for (int m = 0; m < 8; m++) {
        const long r = (long)r0 + ty * 8 + m;
        if (r < TN) {
            const float* erow = Ein + r * NS + c0 + tx * 8;
            float4 e0 = *(const float4*)erow;
            float4 e1 = *(const float4*)(erow + 4);
            float c[8];
#pragma unroll
            for (int p = 0; p < 4; p++)
                asm("mov.b64 {%0, %1}, %2;"
                    : "=f"(c[2 * p]), "=f"(c[2 * p + 1]) : "l"(acc[m][p]));
            float4 o0 = make_float4(c[0] + e0.x, c[1] + e0.y, c[2] + e0.z, c[3] + e0.w);
            float4 o1 = make_float4(c[4] + e1.x, c[5] + e1.y, c[6] + e1.z, c[7] + e1.w);
            float* orow = Eout + r * NS + c0 + tx * 8;
            *(float4*)orow       = o0;
            *(float4*)(orow + 4) = o1;
        }
    }
}

// ---------------- host orchestration (graph-capturable, alloc-free) ----------------
extern "C" void kernel_launch(void* const* d_in, const int* in_sizes, int n_in,
                              void* d_out, int out_size) {
    const float* A  = (const float*)d_in[0];   // [512,512]
    const float* Bm = (const float*)d_in[1];   // [512,9]
    const float* Q  = (const float*)d_in[2];   // [8]
    const float* Tt = (const float*)d_in[3];   // [2000]
    const float* Tv = (const float*)d_in[4];   // [2000]
    const float* iv = (const float*)d_in[5];   // [512]
    // d_in[6] = t_eval (implied by n*DT, unused)
    float* out = (float*)d_out;                // [20000,512]

    float *Ea, *Lt, *G1, *G2, *Wb, *vec;
    cudaGetSymbolAddress((void**)&Ea,  d_Ea);
    cudaGetSymbolAddress((void**)&Lt,  d_Lt);
    cudaGetSymbolAddress((void**)&G1,  d_G1);
    cudaGetSymbolAddress((void**)&G2,  d_G2);
    cudaGetSymbolAddress((void**)&Wb,  d_W);
    cudaGetSymbolAddress((void**)&vec, d_vec);

    // Lt = (dt*A)^T
    k_tpose<<<1024, 256>>>(A, Lt);

    // g = B[:,0], h = B[:,1:] @ Q ; paired L-power chains
    k_gh<<<2, 256>>>(Bm, Q, vec + 0 * NS, vec + 1 * NS);
    k_matvec2<<<512, 128>>>(A, vec + 0 * NS, vec + 1 * NS, vec + 2 * NS, vec + 5 * NS, DTC); // Lg, Lh
    k_matvec2<<<512, 128>>>(A, vec + 2 * NS, vec + 5 * NS, vec + 3 * NS, vec + 6 * NS, DTC); // L2g, L2h
    k_matvec2<<<512, 128>>>(A, vec + 3 * NS, vec + 6 * NS, vec + 4 * NS, vec + 7 * NS, DTC); // L3g, L3h
    k_combine<<<2, 256>>>(vec);                                   // w1..w4, v

    // W0 = M^T = I + Lt(I + Lt/2 (I + Lt/3 (I + Lt/4)))  (Horner)
    dim3 gg(8, 16);
    k_axpyI<<<1024, 256>>>(Lt, G1, 0.25f);
    k_gemm512<<<gg, 128>>>(Lt, G1, G2, 1.0f / 3.0f, 1);
    k_gemm512<<<gg, 128>>>(Lt, G2, G1, 0.5f, 1);
    k_gemm512<<<gg, 128>>>(Lt, G1, Wb, 1.0f, 1);

    // W_{k+1} = W_k @ W_k   (= (M^{2^{k+1}})^T)
    for (int k = 0; k < NLEV - 1; ++k)
        k_gemm512<<<gg, 128>>>(Wb + (size_t)k * NS * NS, Wb + (size_t)k * NS * NS,
                               Wb + (size_t)(k + 1) * NS * NS, 1.0f, 0);

    // E0 rows: [iv, d_0, ..., d_{T-2}]  (built directly into d_out)
    k_buildE0<<<TN, 128>>>(Tt, Tv, iv, vec, out);

    // Hillis-Steele scan; ping-pong out <-> Ea. NLEV=8 (even) ends in `out`.
    float* src = out;
    float* dst = Ea;
    dim3 gs(8, (TN + 127) / 128);
    for (int k = 0; k < NLEV; ++k) {
        k_scan<<<gs, 128>>>(src, Wb + (size_t)k * NS * NS, dst, 1 << k);
        float* tmp = src; src = dst; dst = tmp;
    }
    // result now in `out`
}

// round 8
// speedup vs baseline: 2.1823x; 1.7223x over previous
#include <cuda_runtime.h>

#define NS   512
#define TN   20000
#define ND   2000
#define DTC  30.0f
#define NLEV 8    // tree levels 0..7 ; window 256 ; ||M^256|| ~ 1e-6 (log-norm bound)

// ---------------- static scratch (no allocations allowed) ----------------
__device__ float d_Lt[NS * NS];             // (dt*A)^T
__device__ float d_G1[NS * NS];
__device__ float d_G2[NS * NS];
__device__ float d_W[NLEV][NS * NS];        // W_k = (M^{2^k})^T
__device__ float d_vec[13 * NS];            // g,h,Lg,L2g,L3g,Lh,L2h,L3h,w1..w4,v

// ---------------- small helpers ----------------
__global__ void k_tpose(const float* __restrict__ A, float* __restrict__ Lt) {
    int idx = blockIdx.x * blockDim.x + threadIdx.x;
    if (idx < NS * NS) {
        int i = idx >> 9, j = idx & 511;
        Lt[idx] = DTC * A[j * NS + i];
    }
}

__global__ void k_gh(const float* __restrict__ B, const float* __restrict__ Q,
                     float* __restrict__ g, float* __restrict__ h) {
    int i = blockIdx.x * blockDim.x + threadIdx.x;
    if (i < NS) {
        g[i] = B[i * 9];
        float s = 0.f;
#pragma unroll
        for (int m = 0; m < 8; m++) s += B[i * 9 + 1 + m] * Q[m];
        h[i] = s;
    }
}

// y1 = scale*(A@x1), y2 = scale*(A@x2)   (one block per output row, paired)
__global__ void k_matvec2(const float* __restrict__ A,
                          const float* __restrict__ x1, const float* __restrict__ x2,
                          float* __restrict__ y1, float* __restrict__ y2, float scale) {
    __shared__ float red1[128], red2[128];
    int row = blockIdx.x;
    float s1 = 0.f, s2 = 0.f;
    for (int j = threadIdx.x; j < NS; j += 128) {
        float a = A[row * NS + j];
        s1 += a * x1[j];
        s2 += a * x2[j];
    }
    red1[threadIdx.x] = s1; red2[threadIdx.x] = s2;
    __syncthreads();
    for (int st = 64; st > 0; st >>= 1) {
        if (threadIdx.x < st) {
            red1[threadIdx.x] += red1[threadIdx.x + st];
            red2[threadIdx.x] += red2[threadIdx.x + st];
        }
        __syncthreads();
    }
    if (threadIdx.x == 0) { y1[row] = scale * red1[0]; y2[row] = scale * red2[0]; }
}

// build w1..w4, v from g,h and their L-powers
__global__ void k_combine(float* __restrict__ vec) {
    int i = blockIdx.x * blockDim.x + threadIdx.x;
    if (i >= NS) return;
    const float G   = vec[0 * NS + i], H   = vec[1 * NS + i];
    const float LG  = vec[2 * NS + i], L2G = vec[3 * NS + i], L3G = vec[4 * NS + i];
    const float LH  = vec[5 * NS + i], L2H = vec[6 * NS + i], L3H = vec[7 * NS + i];
    const float c = DTC / 8.0f;
    vec[8  * NS + i] = c * (G + LG + (L2G + L3G) * (1.0f / 3.0f));
    vec[9  * NS + i] = c * (3.0f * G + 2.0f * LG + L2G);
    vec[10 * NS + i] = c * (3.0f * G + LG);
    vec[11 * NS + i] = c * G;
    vec[12 * NS + i] = DTC * (H + 0.5f * LH + L2H * (1.0f / 6.0f) + L3H * (1.0f / 24.0f));
}

// C = alpha*X + I
__global__ void k_axpyI(const float* __restrict__ X, float* __restrict__ C, float alpha) {
    int idx = blockIdx.x * blockDim.x + threadIdx.x;
    if (idx < NS * NS) {
        int i = idx >> 9, j = idx & 511;
        C[idx] = alpha * X[idx] + (i == j ? 1.0f : 0.0f);
    }
}

// ---------------- 512^3 GEMM (latency-optimized): C = alpha*(A@B) + (addI ? I : 0)
// 32x64 tile, 128 threads, f32x2 FMA, grid (8,16) = 128 blocks.
__global__ void __launch_bounds__(128) k_gemm512(
    const float* __restrict__ A, const float* __restrict__ B, float* __restrict__ C,
    float alpha, int addI)
{
    __shared__ float As[16][36];
    __shared__ float Bs[16][68];
    const int t  = threadIdx.x;
    const int tx = t & 7, ty = t >> 3;
    const int r0 = blockIdx.y * 32, c0 = blockIdx.x * 64;

    const int ar = t >> 2, ac4 = (t & 3) * 4;
    const int br = t >> 4, bc4 = (t & 15) * 4;

    unsigned long long acc[2][4];
#pragma unroll
    for (int m = 0; m < 2; m++)
#pragma unroll
        for (int p = 0; p < 4; p++) acc[m][p] = 0ull;

    float4 av = *(const float4*)(A + (size_t)(r0 + ar) * NS + ac4);
    float4 b0 = *(const float4*)(B + (size_t)br * NS + c0 + bc4);
    float4 b1 = *(const float4*)(B + (size_t)(br + 8) * NS + c0 + bc4);

    for (int it = 0; it < 32; ++it) {
        As[ac4 + 0][ar] = av.x; As[ac4 + 1][ar] = av.y;
        As[ac4 + 2][ar] = av.z; As[ac4 + 3][ar] = av.w;
        *(float4*)&Bs[br][bc4]     = b0;
        *(float4*)&Bs[br + 8][bc4] = b1;
        __syncthreads();
        if (it < 31) {
            const int k0 = (it + 1) * 16;
            av = *(const float4*)(A + (size_t)(r0 + ar) * NS + k0 + ac4);
            b0 = *(const float4*)(B + (size_t)(k0 + br) * NS + c0 + bc4);
            b1 = *(const float4*)(B + (size_t)(k0 + br + 8) * NS + c0 + bc4);
        }
#pragma unroll
        for (int kk = 0; kk < 16; ++kk) {
            float a0 = As[kk][ty * 2 + 0];
            float a1 = As[kk][ty * 2 + 1];
            ulonglong2 bp0 = *(const ulonglong2*)&Bs[kk][tx * 8];
            ulonglong2 bp1 = *(const ulonglong2*)&Bs[kk][tx * 8 + 4];
            unsigned long long bv[4] = {bp0.x, bp0.y, bp1.x, bp1.y};
            unsigned long long av0, av1;
            asm("mov.b64 %0, {%1, %1};" : "=l"(av0) : "f"(a0));
            asm("mov.b64 %0, {%1, %1};" : "=l"(av1) : "f"(a1));
#pragma unroll
            for (int p = 0; p < 4; p++) {
                asm("fma.rn.f32x2 %0, %1, %2, %0;" : "+l"(acc[0][p]) : "l"(av0), "l"(bv[p]));
                asm("fma.rn.f32x2 %0, %1, %2, %0;" : "+l"(acc[1][p]) : "l"(av1), "l"(bv[p]));
            }
        }
        __syncthreads();
    }
#pragma unroll
    for (int m = 0; m < 2; m++) {
        const int row = r0 + ty * 2 + m;
#pragma unroll
        for (int p = 0; p < 4; p++) {
            float lo, hi;
            asm("mov.b64 {%0, %1}, %2;" : "=f"(lo), "=f"(hi) : "l"(acc[m][p]));
            int col = c0 + tx * 8 + 2 * p;
            C[(size_t)row * NS + col]     = alpha * lo + ((addI && row == col)     ? 1.0f : 0.0f);
            C[(size_t)row * NS + col + 1] = alpha * hi + ((addI && row == col + 1) ? 1.0f : 0.0f);
        }
    }
}

// ---------------- E0 = [iv ; d_0 ; d_1 ; ... ; d_{T-2}] ----------------
__device__ __forceinline__ float dev_interp(const float* __restrict__ Tt,
                                            const float* __restrict__ Tv, float tq) {
    if (tq <= Tt[0])      return Tv[0];
    if (tq >= Tt[ND - 1]) return Tv[ND - 1];
    int lo = 0, hi = ND - 1;
    while (hi - lo > 1) {
        int mid = (lo + hi) >> 1;
        if (Tt[mid] <= tq) lo = mid; else hi = mid;
    }
    float x0 = Tt[lo], x1 = Tt[lo + 1];
    return Tv[lo] + (tq - x0) * (Tv[lo + 1] - Tv[lo]) / (x1 - x0);
}

__global__ void k_buildE0(const float* __restrict__ Tt, const float* __restrict__ Tv,
                          const float* __restrict__ iv, const float* __restrict__ vec,
                          float* __restrict__ E0)
{
    const int n = blockIdx.x;
    const int t = threadIdx.x;  // 128
    if (n == 0) {
        for (int i = t; i < NS; i += 128) E0[i] = iv[i];
        return;
    }
    __shared__ float s[4];
    if (t < 4) {
        float tq = (float)(n - 1) * DTC + (float)t * 10.0f;  // t, t+dt/3, t+2dt/3, t+dt
        s[t] = dev_interp(Tt, Tv, tq);
    }
    __syncthreads();
    const float s1 = s[0], s2 = s[1], s3 = s[2], s4 = s[3];
    const float* w1 = vec + 8  * NS;
    const float* w2 = vec + 9  * NS;
    const float* w3 = vec + 10 * NS;
    const float* w4 = vec + 11 * NS;
    const float* vv = vec + 12 * NS;
    float* row = E0 + (size_t)n * NS;
    for (int i = t; i < NS; i += 128)
        row[i] = s1 * w1[i] + s2 * w2[i] + s3 * w3[i] + s4 * w4[i] + vv[i];
}

// ---------------- Brent-Kung tree edge: V[o*S+boff] += V[o*S+aoff] @ W, o in [0,cnt)
// In place: within a level, source rows and dest rows are disjoint residues mod S.
// 128(logical-op) x 64(col) tile, 128 threads, 8x8 per thread, f32x2 FMA, occ 4.
__global__ void __launch_bounds__(128, 4) k_bk(
    float* __restrict__ V, const float* __restrict__ W,
    int S, int aoff, int boff, int cnt)
{
    __shared__ float As[16][132];   // transposed A tile [k][row], +4 pad
    __shared__ float Bs[16][68];    // B tile [k][col], +4 pad

    const int t  = threadIdx.x;
    const int tx = t & 7;           // 0..7  -> 8 output cols
    const int ty = t >> 3;          // 0..15 -> 8 output rows
    const int r0 = blockIdx.y * 128;
    const int c0 = blockIdx.x * 64;

    // A (gathered source rows): 128 logical rows x 16 cols. 4 float4 per thread.
    const int  ar  = t >> 2;        // 0..31
    const int  ac4 = (t & 3) * 4;   // 0,4,8,12
    long gr[4]; bool v[4];
#pragma unroll
    for (int g = 0; g < 4; g++) {
        int lo = r0 + ar + 32 * g;
        v[g]  = lo < cnt;
        gr[g] = (long)lo * S + aoff;
    }

    // B (W): 16 rows x 64 cols. Thread loads 2 float4 (k rows br, br+8).
    const int br  = t >> 4;         // 0..7
    const int bc4 = (t & 15) * 4;   // 0..60

    unsigned long long acc[8][4];
#pragma unroll
    for (int m = 0; m < 8; m++)
#pragma unroll
        for (int p = 0; p < 4; p++) acc[m][p] = 0ull;

    const float4 f4z = make_float4(0.f, 0.f, 0.f, 0.f);
    float4 av[4], b0, b1;
#pragma unroll
    for (int g = 0; g < 4; g++)
        av[g] = v[g] ? *(const float4*)(V + gr[g] * NS + ac4) : f4z;
    b0 = *(const float4*)(W + (size_t)br * NS + c0 + bc4);
    b1 = *(const float4*)(W + (size_t)(br + 8) * NS + c0 + bc4);

    for (int it = 0; it < 32; ++it) {
#pragma unroll
        for (int g = 0; g < 4; g++) {
            As[ac4 + 0][ar + 32 * g] = av[g].x;
            As[ac4 + 1][ar + 32 * g] = av[g].y;
            As[ac4 + 2][ar + 32 * g] = av[g].z;
            As[ac4 + 3][ar + 32 * g] = av[g].w;
        }
        *(float4*)&Bs[br][bc4]     = b0;
        *(float4*)&Bs[br + 8][bc4] = b1;
        __syncthreads();

        if (it < 31) {  // stage next tile while computing
            const int k0 = (it + 1) * 16;
#pragma unroll
            for (int g = 0; g < 4; g++)
                av[g] = v[g] ? *(const float4*)(V + gr[g] * NS + k0 + ac4) : f4z;
            b0 = *(const float4*)(W + (size_t)(k0 + br) * NS + c0 + bc4);
            b1 = *(const float4*)(W + (size_t)(k0 + br + 8) * NS + c0 + bc4);
        }

#pragma unroll
        for (int kk = 0; kk < 16; ++kk) {
            float a[8];
            *(float4*)&a[0] = *(const float4*)&As[kk][ty * 8];
            *(float4*)&a[4] = *(const float4*)&As[kk][ty * 8 + 4];
            ulonglong2 bp0 = *(const ulonglong2*)&Bs[kk][tx * 8];
            ulonglong2 bp1 = *(const ulonglong2*)&Bs[kk][tx * 8 + 4];
            unsigned long long bv[4] = {bp0.x, bp0.y, bp1.x, bp1.y};
#pragma unroll
            for (int m = 0; m < 8; m++) {
                unsigned long long avv;
                asm("mov.b64 %0, {%1, %1};" : "=l"(avv) : "f"(a[m]));
#pragma unroll
                for (int p = 0; p < 4; p++)
                    asm("fma.rn.f32x2 %0, %1, %2, %0;"
                        : "+l"(acc[m][p]) : "l"(avv), "l"(bv[p]));
            }
        }
        __syncthreads();
    }

    // epilogue: in-place accumulate into dest rows
#pragma unroll
    for (int m = 0; m < 8; m++) {
        const int r = r0 + ty * 8 + m;
        if (r < cnt) {
            const long dr = (long)r * S + boff;
            float* erow = V + dr * NS + c0 + tx * 8;
            float4 e0 = *(const float4*)erow;
            float4 e1 = *(const float4*)(erow + 4);
            float c[8];
#pragma unroll
            for (int p = 0; p < 4; p++)
                asm("mov.b64 {%0, %1}, %2;"
                    : "=f"(c[2 * p]), "=f"(c[2 * p + 1]) : "l"(acc[m][p]));
            float4 o0 = make_float4(c[0] + e0.x, c[1] + e0.y, c[2] + e0.z, c[3] + e0.w);
            float4 o1 = make_float4(c[4] + e1.x, c[5] + e1.y, c[6] + e1.z, c[7] + e1.w);
            *(float4*)erow       = o0;
            *(float4*)(erow + 4) = o1;
        }
    }
}

// ---------------- host orchestration (graph-capturable, alloc-free) ----------------
extern "C" void kernel_launch(void* const* d_in, const int* in_sizes, int n_in,
                              void* d_out, int out_size) {
    const float* A  = (const float*)d_in[0];   // [512,512]
    const float* Bm = (const float*)d_in[1];   // [512,9]
    const float* Q  = (const float*)d_in[2];   // [8]
    const float* Tt = (const float*)d_in[3];   // [2000]
    const float* Tv = (const float*)d_in[4];   // [2000]
    const float* iv = (const float*)d_in[5];   // [512]
    // d_in[6] = t_eval (implied by n*DT, unused)
    float* out = (float*)d_out;                // [20000,512]

    float *Lt, *G1, *G2, *Wb, *vec;
    cudaGetSymbolAddress((void**)&Lt,  d_Lt);
    cudaGetSymbolAddress((void**)&G1,  d_G1);
    cudaGetSymbolAddress((void**)&G2,  d_G2);
    cudaGetSymbolAddress((void**)&Wb,  d_W);
    cudaGetSymbolAddress((void**)&vec, d_vec);

    // Lt = (dt*A)^T
    k_tpose<<<1024, 256>>>(A, Lt);

    // g = B[:,0], h = B[:,1:] @ Q ; paired L-power chains
    k_gh<<<2, 256>>>(Bm, Q, vec + 0 * NS, vec + 1 * NS);
    k_matvec2<<<512, 128>>>(A, vec + 0 * NS, vec + 1 * NS, vec + 2 * NS, vec + 5 * NS, DTC);
    k_matvec2<<<512, 128>>>(A, vec + 2 * NS, vec + 5 * NS, vec + 3 * NS, vec + 6 * NS, DTC);
    k_matvec2<<<512, 128>>>(A, vec + 3 * NS, vec + 6 * NS, vec + 4 * NS, vec + 7 * NS, DTC);
    k_combine<<<2, 256>>>(vec);                                   // w1..w4, v

    // W0 = M^T = I + Lt(I + Lt/2 (I + Lt/3 (I + Lt/4)))  (Horner)
    dim3 gg(8, 16);
    k_axpyI<<<1024, 256>>>(Lt, G1, 0.25f);
    k_gemm512<<<gg, 128>>>(Lt, G1, G2, 1.0f / 3.0f, 1);
    k_gemm512<<<gg, 128>>>(Lt, G2, G1, 0.5f, 1);
    k_gemm512<<<gg, 128>>>(Lt, G1, Wb, 1.0f, 1);

    // W_{k+1} = W_k @ W_k   (= (M^{2^{k+1}})^T)
    for (int k = 0; k < NLEV - 1; ++k)
        k_gemm512<<<gg, 128>>>(Wb + (size_t)k * NS * NS, Wb + (size_t)k * NS * NS,
                               Wb + (size_t)(k + 1) * NS * NS, 1.0f, 0);

    // E0 rows: [iv, d_0, ..., d_{T-2}]  (built directly into d_out)
    k_buildE0<<<TN, 128>>>(Tt, Tv, iv, vec, out);

    // ---- Brent-Kung up-sweep: V[o*S + S-1] += W_k * V[o*S + 2^k - 1]
    for (int k = 0; k < NLEV; ++k) {
        const int S = 1 << (k + 1);
        const int cnt = TN / S;
        dim3 gs(8, (cnt + 127) / 128);
        k_bk<<<gs, 128>>>(out, Wb + (size_t)k * NS * NS,
                          S, (1 << k) - 1, S - 1, cnt);
    }
    // ---- Brent-Kung down-sweep: V[o*S + S-1 + 2^k] += W_k * V[o*S + S-1]
    for (int k = NLEV - 1; k >= 0; --k) {
        const int S = 1 << (k + 1);
        const int boff = S - 1 + (1 << k);
        const int cnt = (TN - 1 - boff) / S + 1;
        dim3 gs(8, (cnt + 127) / 128);
        k_bk<<<gs, 128>>>(out, Wb + (size_t)k * NS * NS,
                          S, S - 1, boff, cnt);
    }
    // result in `out`
}

// round 9
// speedup vs baseline: 3.3696x; 1.5440x over previous
#include <cuda_runtime.h>

#define NS   512
#define TN   20000
#define ND   2000
#define DTC  30.0f
#define NLEV 8      // window 256 ; ||M^256|| ~ 1e-6

#define SKROWS 640  // split-K partial buffer rows (covers cnt <= 640 levels)

// ---------------- static scratch (no allocations allowed) ----------------
__device__ float d_Lt[NS * NS];             // (dt*A)^T
__device__ float d_G1[NS * NS];
__device__ float d_G2[NS * NS];
__device__ float d_W[NLEV][NS * NS];        // W_k = (M^{2^k})^T
__device__ float d_vec[35 * NS];
__device__ float d_part[4 * SKROWS * NS];   // split-K partials (5.2 MB)

// vec slots (x NS):
// 0-7  : g,h,Lg,L2g,L3g,Lh,L2h,L3h   (temps; slot 0 reused for iv after combine)
// 8-11 : w1..w4  (= M^0 w)
// 12   : v
// 13-16: M w1..w4      17-20: M^2 w     21-24: M^3 w
// 25   : Mv   26: M^2 v   27: M^3 v
// 28   : M iv 29: M^2 iv  30: M^3 iv
// 31   : cv2 = v+Mv      32: cv4 = v+Mv+M^2v+M^3v
// 33   : b1  = v+Miv     34: b3  = v+Mv+M^2v+M^3iv

// ---------------- small helpers ----------------
__global__ void k_tpose(const float* __restrict__ A, float* __restrict__ Lt) {
    int idx = blockIdx.x * blockDim.x + threadIdx.x;
    if (idx < NS * NS) {
        int i = idx >> 9, j = idx & 511;
        Lt[idx] = DTC * A[j * NS + i];
    }
}

__global__ void k_gh(const float* __restrict__ B, const float* __restrict__ Q,
                     float* __restrict__ g, float* __restrict__ h) {
    int i = blockIdx.x * blockDim.x + threadIdx.x;
    if (i < NS) {
        g[i] = B[i * 9];
        float s = 0.f;
#pragma unroll
        for (int m = 0; m < 8; m++) s += B[i * 9 + 1 + m] * Q[m];
        h[i] = s;
    }
}

__global__ void k_matvec2(const float* __restrict__ A,
                          const float* __restrict__ x1, const float* __restrict__ x2,
                          float* __restrict__ y1, float* __restrict__ y2, float scale) {
    __shared__ float red1[128], red2[128];
    int row = blockIdx.x;
    float s1 = 0.f, s2 = 0.f;
    for (int j = threadIdx.x; j < NS; j += 128) {
        float a = A[row * NS + j];
        s1 += a * x1[j];
        s2 += a * x2[j];
    }
    red1[threadIdx.x] = s1; red2[threadIdx.x] = s2;
    __syncthreads();
    for (int st = 64; st > 0; st >>= 1) {
        if (threadIdx.x < st) {
            red1[threadIdx.x] += red1[threadIdx.x + st];
            red2[threadIdx.x] += red2[threadIdx.x + st];
        }
        __syncthreads();
    }
    if (threadIdx.x == 0) { y1[row] = scale * red1[0]; y2[row] = scale * red2[0]; }
}

__global__ void k_combine(float* __restrict__ vec) {
    int i = blockIdx.x * blockDim.x + threadIdx.x;
    if (i >= NS) return;
    const float G   = vec[0 * NS + i], H   = vec[1 * NS + i];
    const float LG  = vec[2 * NS + i], L2G = vec[3 * NS + i], L3G = vec[4 * NS + i];
    const float LH  = vec[5 * NS + i], L2H = vec[6 * NS + i], L3H = vec[7 * NS + i];
    const float c = DTC / 8.0f;
    vec[8  * NS + i] = c * (G + LG + (L2G + L3G) * (1.0f / 3.0f));
    vec[9  * NS + i] = c * (3.0f * G + 2.0f * LG + L2G);
    vec[10 * NS + i] = c * (3.0f * G + LG);
    vec[11 * NS + i] = c * G;
    vec[12 * NS + i] = DTC * (H + 0.5f * LH + L2H * (1.0f / 6.0f) + L3H * (1.0f / 24.0f));
}

__global__ void k_copyiv(const float* __restrict__ iv, float* __restrict__ vec) {
    int i = blockIdx.x * blockDim.x + threadIdx.x;
    if (i < NS) vec[i] = iv[i];   // slot 0
}

// y = M @ x for 6 vectors, using W0 = M^T:  y[c] = sum_j W0[j][c] * x[j]
// grid (8, 6), 256 threads: 64 cols x 4 j-chunks.
__global__ void k_vecmat6(const float* __restrict__ W, float* __restrict__ vec,
                          int s0, int s1, int s2, int s3, int s4, int s5,
                          int t0, int t1, int t2, int t3, int t4, int t5) {
    int ss[6] = {s0, s1, s2, s3, s4, s5};
    int tt[6] = {t0, t1, t2, t3, t4, t5};
    const float* x = vec + ss[blockIdx.y] * NS;
    float*       y = vec + tt[blockIdx.y] * NS;

    __shared__ float xs[NS];
    __shared__ float red[256];
    int t = threadIdx.x;
    for (int i = t; i < NS; i += 256) xs[i] = x[i];
    __syncthreads();

    int cl = t & 63, jc = t >> 6;
    int c  = blockIdx.x * 64 + cl;
    float acc = 0.f;
    int j0 = jc * 128;
#pragma unroll 8
    for (int j = j0; j < j0 + 128; ++j) acc += W[j * NS + c] * xs[j];
    red[t] = acc;
    __syncthreads();
    if (jc == 0) y[c] = red[t] + red[t + 64] + red[t + 128] + red[t + 192];
}

// cv2, cv4, b1, b3 combos
__global__ void k_finvec(float* __restrict__ vec) {
    int i = blockIdx.x * blockDim.x + threadIdx.x;
    if (i >= NS) return;
    float v  = vec[12 * NS + i];
    float mv = vec[25 * NS + i], m2v = vec[26 * NS + i], m3v = vec[27 * NS + i];
    float miv = vec[28 * NS + i], m3iv = vec[30 * NS + i];
    vec[31 * NS + i] = v + mv;                 // cv2
    vec[32 * NS + i] = v + mv + m2v + m3v;     // cv4
    vec[33 * NS + i] = v + miv;                // b1 (row 1)
    vec[34 * NS + i] = v + mv + m2v + m3iv;    // b3 (row 3)
}

// C = alpha*X + I
__global__ void k_axpyI(const float* __restrict__ X, float* __restrict__ C, float alpha) {
    int idx = blockIdx.x * blockDim.x + threadIdx.x;
    if (idx < NS * NS) {
        int i = idx >> 9, j = idx & 511;
        C[idx] = alpha * X[idx] + (i == j ? 1.0f : 0.0f);
    }
}

// ---------------- 512^3 GEMM: C = alpha*(A@B) + (addI ? I : 0) ----------------
__global__ void __launch_bounds__(128) k_gemm512(
    const float* __restrict__ A, const float* __restrict__ B, float* __restrict__ C,
    float alpha, int addI)
{
    __shared__ float As[16][36];
    __shared__ float Bs[16][68];
    const int t  = threadIdx.x;
    const int tx = t & 7, ty = t >> 3;
    const int r0 = blockIdx.y * 32, c0 = blockIdx.x * 64;

    const int ar = t >> 2, ac4 = (t & 3) * 4;
    const int br = t >> 4, bc4 = (t & 15) * 4;

    unsigned long long acc[2][4];
#pragma unroll
    for (int m = 0; m < 2; m++)
#pragma unroll
        for (int p = 0; p < 4; p++) acc[m][p] = 0ull;

    float4 av = *(const float4*)(A + (size_t)(r0 + ar) * NS + ac4);
    float4 b0 = *(const float4*)(B + (size_t)br * NS + c0 + bc4);
    float4 b1 = *(const float4*)(B + (size_t)(br + 8) * NS + c0 + bc4);

    for (int it = 0; it < 32; ++it) {
        As[ac4 + 0][ar] = av.x; As[ac4 + 1][ar] = av.y;
        As[ac4 + 2][ar] = av.z; As[ac4 + 3][ar] = av.w;
        *(float4*)&Bs[br][bc4]     = b0;
        *(float4*)&Bs[br + 8][bc4] = b1;
        __syncthreads();
        if (it < 31) {
            const int k0 = (it + 1) * 16;
            av = *(const float4*)(A + (size_t)(r0 + ar) * NS + k0 + ac4);
            b0 = *(const float4*)(B + (size_t)(k0 + br) * NS + c0 + bc4);
            b1 = *(const float4*)(B + (size_t)(k0 + br + 8) * NS + c0 + bc4);
        }
#pragma unroll
        for (int kk = 0; kk < 16; ++kk) {
            float a0 = As[kk][ty * 2 + 0];
            float a1 = As[kk][ty * 2 + 1];
            ulonglong2 bp0 = *(const ulonglong2*)&Bs[kk][tx * 8];
            ulonglong2 bp1 = *(const ulonglong2*)&Bs[kk][tx * 8 + 4];
            unsigned long long bv[4] = {bp0.x, bp0.y, bp1.x, bp1.y};
            unsigned long long av0, av1;
            asm("mov.b64 %0, {%1, %1};" : "=l"(av0) : "f"(a0));
            asm("mov.b64 %0, {%1, %1};" : "=l"(av1) : "f"(a1));
#pragma unroll
            for (int p = 0; p < 4; p++) {
                asm("fma.rn.f32x2 %0, %1, %2, %0;" : "+l"(acc[0][p]) : "l"(av0), "l"(bv[p]));
                asm("fma.rn.f32x2 %0, %1, %2, %0;" : "+l"(acc[1][p]) : "l"(av1), "l"(bv[p]));
            }
        }
        __syncthreads();
    }
#pragma unroll
    for (int m = 0; m < 2; m++) {
        const int row = r0 + ty * 2 + m;
#pragma unroll
        for (int p = 0; p < 4; p++) {
            float lo, hi;
            asm("mov.b64 {%0, %1}, %2;" : "=f"(lo), "=f"(hi) : "l"(acc[m][p]));
            int col = c0 + tx * 8 + 2 * p;
            C[(size_t)row * NS + col]     = alpha * lo + ((addI && row == col)     ? 1.0f : 0.0f);
            C[(size_t)row * NS + col + 1] = alpha * hi + ((addI && row == col + 1) ? 1.0f : 0.0f);
        }
    }
}

// ---------------- E0 with direct pair/quad partials ----------------
__device__ __forceinline__ float dev_interp(const float* __restrict__ Tt,
                                            const float* __restrict__ Tv, float tq) {
    if (tq <= Tt[0])      return Tv[0];
    if (tq >= Tt[ND - 1]) return Tv[ND - 1];
    int lo = 0, hi = ND - 1;
    while (hi - lo > 1) {
        int mid = (lo + hi) >> 1;
        if (Tt[mid] <= tq) lo = mid; else hi = mid;
    }
    float x0 = Tt[lo], x1 = Tt[lo + 1];
    return Tv[lo] + (tq - x0) * (Tv[lo + 1] - Tv[lo]) / (x1 - x0);
}

// Row n:
//  n == 0          : iv
//  n even          : d_{n-1}                                  (J=1, cons=v)
//  n == 1          : d_0 + M iv                               (J=1, cons=b1)
//  n == 3          : d_2 + M d_1 + M^2 d_0 + M^3 iv           (J=3, cons=b3)
//  n % 4 == 1, n>=5: d_{n-1} + M d_{n-2}                      (J=2, cons=cv2)
//  n % 4 == 3, n>=7: sum_{j<4} M^j d_{n-1-j}                  (J=4, cons=cv4)
__global__ void k_buildE0(const float* __restrict__ Tt, const float* __restrict__ Tv,
                          const float* __restrict__ iv, const float* __restrict__ vec,
                          float* __restrict__ E0)
{
    const int n = blockIdx.x;
    const int t = threadIdx.x;  // 128
    if (n == 0) {
        for (int i = t; i < NS; i += 128) E0[i] = iv[i];
        return;
    }
    int J, cons;
    const int m = n & 3;
    if (m == 1)      { if (n == 1) { J = 1; cons = 33; } else { J = 2; cons = 31; } }
    else if (m == 3) { if (n == 3) { J = 3; cons = 34; } else { J = 4; cons = 32; } }
    else             { J = 1; cons = 12; }

    __shared__ float s[4][4];
    if (t < 4 * J) {
        int jj = t >> 2, ii = t & 3;
        float tq = (float)(n - 1 - jj) * DTC + (float)ii * 10.0f;
        s[jj][ii] = dev_interp(Tt, Tv, tq);
    }
    __syncthreads();

    const int mwslot[4] = {8, 13, 17, 21};   // M^j w blocks (4 contiguous vectors each)
    float* row = E0 + (size_t)n * NS;
    for (int i = t; i < NS; i += 128) {
        float acc = vec[cons * NS + i];
        for (int jj = 0; jj < J; ++jj) {
            const float* base = vec + mwslot[jj] * NS;
            acc += s[jj][0] * base[i]          + s[jj][1] * base[NS + i]
                 + s[jj][2] * base[2 * NS + i] + s[jj][3] * base[3 * NS + i];
        }
        row[i] = acc;
    }
}

// ---------------- Brent-Kung tree edge (in place): V[o*S+boff] += V[o*S+aoff] @ W
__global__ void __launch_bounds__(128, 4) k_bk(
    float* __restrict__ V, const float* __restrict__ W,
    int S, int aoff, int boff, int cnt)
{
    __shared__ float As[16][132];
    __shared__ float Bs[16][68];

    const int t  = threadIdx.x;
    const int tx = t & 7;
    const int ty = t >> 3;
    const int r0 = blockIdx.y * 128;
    const int c0 = blockIdx.x * 64;

    const int  ar  = t >> 2;
    const int  ac4 = (t & 3) * 4;
    long gr[4]; bool v[4];
#pragma unroll
    for (int g = 0; g < 4; g++) {
        int lo = r0 + ar + 32 * g;
        v[g]  = lo < cnt;
        gr[g] = (long)lo * S + aoff;
    }

    const int br  = t >> 4;
    const int bc4 = (t & 15) * 4;

    unsigned long long acc[8][4];
#pragma unroll
    for (int m = 0; m < 8; m++)
#pragma unroll
        for (int p = 0; p < 4; p++) acc[m][p] = 0ull;

    const float4 f4z = make_float4(0.f, 0.f, 0.f, 0.f);
    float4 av[4], b0, b1;
#pragma unroll
    for (int g = 0; g < 4; g++)
        av[g] = v[g] ? *(const float4*)(V + gr[g] * NS + ac4) : f4z;
    b0 = *(const float4*)(W + (size_t)br * NS + c0 + bc4);
    b1 = *(const float4*)(W + (size_t)(br + 8) * NS + c0 + bc4);

    for (int it = 0; it < 32; ++it) {
#pragma unroll
        for (int g = 0; g < 4; g++) {
            As[ac4 + 0][ar + 32 * g] = av[g].x;
            As[ac4 + 1][ar + 32 * g] = av[g].y;
            As[ac4 + 2][ar + 32 * g] = av[g].z;
            As[ac4 + 3][ar + 32 * g] = av[g].w;
        }
        *(float4*)&Bs[br][bc4]     = b0;
        *(float4*)&Bs[br + 8][bc4] = b1;
        __syncthreads();

        if (it < 31) {
            const int k0 = (it + 1) * 16;
#pragma unroll
            for (int g = 0; g < 4; g++)
                av[g] = v[g] ? *(const float4*)(V + gr[g] * NS + k0 + ac4) : f4z;
            b0 = *(const float4*)(W + (size_t)(k0 + br) * NS + c0 + bc4);
            b1 = *(const float4*)(W + (size_t)(k0 + br + 8) * NS + c0 + bc4);
        }

#pragma unroll
        for (int kk = 0; kk < 16; ++kk) {
            float a[8];
            *(float4*)&a[0] = *(const float4*)&As[kk][ty * 8];
            *(float4*)&a[4] = *(const float4*)&As[kk][ty * 8 + 4];
            ulonglong2 bp0 = *(const ulonglong2*)&Bs[kk][tx * 8];
            ulonglong2 bp1 = *(const ulonglong2*)&Bs[kk][tx * 8 + 4];
            unsigned long long bv[4] = {bp0.x, bp0.y, bp1.x, bp1.y};
#pragma unroll
            for (int m = 0; m < 8; m++) {
                unsigned long long avv;
                asm("mov.b64 %0, {%1, %1};" : "=l"(avv) : "f"(a[m]));
#pragma unroll
                for (int p = 0; p < 4; p++)
                    asm("fma.rn.f32x2 %0, %1, %2, %0;"
                        : "+l"(acc[m][p]) : "l"(avv), "l"(bv[p]));
            }
        }
        __syncthreads();
    }

#pragma unroll
    for (int m = 0; m < 8; m++) {
        const int r = r0 + ty * 8 + m;
        if (r < cnt) {
            const long dr = (long)r * S + boff;
            float* erow = V + dr * NS + c0 + tx * 8;
            float4 e0 = *(const float4*)erow;
            float4 e1 = *(const float4*)(erow + 4);
            float c[8];
#pragma unroll
            for (int p = 0; p < 4; p++)
                asm("mov.b64 {%0, %1}, %2;"
                    : "=f"(c[2 * p]), "=f"(c[2 * p + 1]) : "l"(acc[m][p]));
            float4 o0 = make_float4(c[0] + e0.x, c[1] + e0.y, c[2] + e0.z, c[3] + e0.w);
            float4 o1 = make_float4(c[4] + e1.x, c[5] + e1.y, c[6] + e1.z, c[7] + e1.w);
            *(float4*)erow       = o0;
            *(float4*)(erow + 4) = o1;
        }
    }
}

// ---------------- split-K (x4) variant for small levels: writes partials ----------------
__global__ void __launch_bounds__(128, 4) k_bk_sk(
    const float* __restrict__ V, const float* __restrict__ W,
    float* __restrict__ part, int S, int aoff, int cnt)
{
    __shared__ float As[16][132];
    __shared__ float Bs[16][68];

    const int t  = threadIdx.x;
    const int tx = t & 7;
    const int ty = t >> 3;
    const int r0 = blockIdx.y * 128;
    const int c0 = blockIdx.x * 64;
    const int z  = blockIdx.z;
    const int kb = z * 128;

    const int  ar  = t >> 2;
    const int  ac4 = (t & 3) * 4;
    long gr[4]; bool v[4];
#pragma unroll
    for (int g = 0; g < 4; g++) {
        int lo = r0 + ar + 32 * g;
        v[g]  = lo < cnt;
        gr[g] = (long)lo * S + aoff;
    }

    const int br  = t >> 4;
    const int bc4 = (t & 15) * 4;

    unsigned long long acc[8][4];
#pragma unroll
    for (int m = 0; m < 8; m++)
#pragma unroll
        for (int p = 0; p < 4; p++) acc[m][p] = 0ull;

    const float4 f4z = make_float4(0.f, 0.f, 0.f, 0.f);
    float4 av[4], b0, b1;
#pragma unroll
    for (int g = 0; g < 4; g++)
        av[g] = v[g] ? *(const float4*)(V + gr[g] * NS + kb + ac4) : f4z;
    b0 = *(const float4*)(W + (size_t)(kb + br) * NS + c0 + bc4);
    b1 = *(const float4*)(W + (size_t)(kb + br + 8) * NS + c0 + bc4);

    for (int it = 0; it < 8; ++it) {
#pragma unroll
        for (int g = 0; g < 4; g++) {
            As[ac4 + 0][ar + 32 * g] = av[g].x;
            As[ac4 + 1][ar + 32 * g] = av[g].y;
            As[ac4 + 2][ar + 32 * g] = av[g].z;
            As[ac4 + 3][ar + 32 * g] = av[g].w;
        }
        *(float4*)&Bs[br][bc4]     = b0;
        *(float4*)&Bs[br + 8][bc4] = b1;
        __syncthreads();

        if (it < 7) {
            const int k0 = kb + (it + 1) * 16;
#pragma unroll
            for (int g = 0; g < 4; g++)
                av[g] = v[g] ? *(const float4*)(V + gr[g] * NS + k0 + ac4) : f4z;
            b0 = *(const float4*)(W + (size_t)(k0 + br) * NS + c0 + bc4);
            b1 = *(const float4*)(W + (size_t)(k0 + br + 8) * NS + c0 + bc4);
        }

#pragma unroll
        for (int kk = 0; kk < 16; ++kk) {
            float a[8];
            *(float4*)&a[0] = *(const float4*)&As[kk][ty * 8];
            *(float4*)&a[4] = *(const float4*)&As[kk][ty * 8 + 4];
            ulonglong2 bp0 = *(const ulonglong2*)&Bs[kk][tx * 8];
            ulonglong2 bp1 = *(const ulonglong2*)&Bs[kk][tx * 8 + 4];
            unsigned long long bv[4] = {bp0.x, bp0.y, bp1.x, bp1.y};
#pragma unroll
            for (int m = 0; m < 8; m++) {
                unsigned long long avv;
                asm("mov.b64 %0, {%1, %1};" : "=l"(avv) : "f"(a[m]));
#pragma unroll
                for (int p = 0; p < 4; p++)
                    asm("fma.rn.f32x2 %0, %1, %2, %0;"
                        : "+l"(acc[m][p]) : "l"(avv), "l"(bv[p]));
            }
        }
        __syncthreads();
    }

#pragma unroll
    for (int m = 0; m < 8; m++) {
        const int r = r0 + ty * 8 + m;
        if (r < cnt) {
            float c[8];
#pragma unroll
            for (int p = 0; p < 4; p++)
                asm("mov.b64 {%0, %1}, %2;"
                    : "=f"(c[2 * p]), "=f"(c[2 * p + 1]) : "l"(acc[m][p]));
            float* prow = part + ((size_t)z * SKROWS + r) * NS + c0 + tx * 8;
            *(float4*)prow       = make_float4(c[0], c[1], c[2], c[3]);
            *(float4*)(prow + 4) = make_float4(c[4], c[5], c[6], c[7]);
        }
    }
}

// deterministic reduce of the 4 partials into dest rows
__global__ void k_bk_red(float* __restrict__ V, const float* __restrict__ part,
                         int S, int boff, int cnt)
{
    int idx = blockIdx.x * 256 + threadIdx.x;
    int total = cnt * (NS / 4);
    if (idx >= total) return;
    int r  = idx / (NS / 4);
    int c4 = (idx - r * (NS / 4)) * 4;
    float4 p0 = *(const float4*)(part + ((size_t)0 * SKROWS + r) * NS + c4);
    float4 p1 = *(const float4*)(part + ((size_t)1 * SKROWS + r) * NS + c4);
    float4 p2 = *(const float4*)(part + ((size_t)2 * SKROWS + r) * NS + c4);
    float4 p3 = *(const float4*)(part + ((size_t)3 * SKROWS + r) * NS + c4);
    float* dst = V + ((size_t)r * S + boff) * NS + c4;
    float4 d = *(const float4*)dst;
    d.x += (p0.x + p1.x) + (p2.x + p3.x);
    d.y += (p0.y + p1.y) + (p2.y + p3.y);
    d.z += (p0.z + p1.z) + (p2.z + p3.z);
    d.w += (p0.w + p1.w) + (p2.w + p3.w);
    *(float4*)dst = d;
}

// ---------------- host orchestration (graph-capturable, alloc-free) ----------------
extern "C" void kernel_launch(void* const* d_in, const int* in_sizes, int n_in,
                              void* d_out, int out_size) {
    const float* A  = (const float*)d_in[0];
    const float* Bm = (const float*)d_in[1];
    const float* Q  = (const float*)d_in[2];
    const float* Tt = (const float*)d_in[3];
    const float* Tv = (const float*)d_in[4];
    const float* iv = (const float*)d_in[5];
    float* out = (float*)d_out;

    float *Lt, *G1, *G2, *Wb, *vec, *part;
    cudaGetSymbolAddress((void**)&Lt,   d_Lt);
    cudaGetSymbolAddress((void**)&G1,   d_G1);
    cudaGetSymbolAddress((void**)&G2,   d_G2);
    cudaGetSymbolAddress((void**)&Wb,   d_W);
    cudaGetSymbolAddress((void**)&vec,  d_vec);
    cudaGetSymbolAddress((void**)&part, d_part);

    // Lt = (dt*A)^T
    k_tpose<<<1024, 256>>>(A, Lt);

    // forcing vectors
    k_gh<<<2, 256>>>(Bm, Q, vec + 0 * NS, vec + 1 * NS);
    k_matvec2<<<512, 128>>>(A, vec + 0 * NS, vec + 1 * NS, vec + 2 * NS, vec + 5 * NS, DTC);
    k_matvec2<<<512, 128>>>(A, vec + 2 * NS, vec + 5 * NS, vec + 3 * NS, vec + 6 * NS, DTC);
    k_matvec2<<<512, 128>>>(A, vec + 3 * NS, vec + 6 * NS, vec + 4 * NS, vec + 7 * NS, DTC);
    k_combine<<<2, 256>>>(vec);                  // w1..w4 (8-11), v (12)
    k_copyiv<<<2, 256>>>(iv, vec);               // iv -> slot 0

    // W0 = M^T via Horner
    dim3 gg(8, 16);
    k_axpyI<<<1024, 256>>>(Lt, G1, 0.25f);
    k_gemm512<<<gg, 128>>>(Lt, G1, G2, 1.0f / 3.0f, 1);
    k_gemm512<<<gg, 128>>>(Lt, G2, G1, 0.5f, 1);
    k_gemm512<<<gg, 128>>>(Lt, G1, Wb, 1.0f, 1);

    // M^j chains on [w1..w4, v, iv] using W0
    dim3 gv(8, 6);
    k_vecmat6<<<gv, 256>>>(Wb, vec, 8, 9, 10, 11, 12, 0,   13, 14, 15, 16, 25, 28);
    k_vecmat6<<<gv, 256>>>(Wb, vec, 13, 14, 15, 16, 25, 28, 17, 18, 19, 20, 26, 29);
    k_vecmat6<<<gv, 256>>>(Wb, vec, 17, 18, 19, 20, 26, 29, 21, 22, 23, 24, 27, 30);
    k_finvec<<<2, 256>>>(vec);

    // W_{k+1} = W_k @ W_k
    for (int k = 0; k < NLEV - 1; ++k)
        k_gemm512<<<gg, 128>>>(Wb + (size_t)k * NS * NS, Wb + (size_t)k * NS * NS,
                               Wb + (size_t)(k + 1) * NS * NS, 1.0f, 0);

    // E0 with direct pair/quad partials (kills up-sweep levels 0 and 1)
    k_buildE0<<<TN, 128>>>(Tt, Tv, iv, vec, out);

    // ---- up-sweep, levels 2..7
    for (int k = 2; k < NLEV; ++k) {
        const int S = 1 << (k + 1);
        const int aoff = (1 << k) - 1, boff = S - 1;
        const int cnt = TN / S;
        if (cnt <= SKROWS) {
            dim3 gs(8, (cnt + 127) / 128, 4);
            k_bk_sk<<<gs, 128>>>(out, Wb + (size_t)k * NS * NS, part, S, aoff, cnt);
            k_bk_red<<<(cnt * (NS / 4) + 255) / 256, 256>>>(out, part, S, boff, cnt);
        } else {
            dim3 gs(8, (cnt + 127) / 128);
            k_bk<<<gs, 128>>>(out, Wb + (size_t)k * NS * NS, S, aoff, boff, cnt);
        }
    }
    // ---- down-sweep, levels 7..0
    for (int k = NLEV - 1; k >= 0; --k) {
        const int S = 1 << (k + 1);
        const int aoff = S - 1, boff = S - 1 + (1 << k);
        const int cnt = (TN - 1 - boff) / S + 1;
        if (cnt <= SKROWS) {
            dim3 gs(8, (cnt + 127) / 128, 4);
            k_bk_sk<<<gs, 128>>>(out, Wb + (size_t)k * NS * NS, part, S, aoff, cnt);
            k_bk_red<<<(cnt * (NS / 4) + 255) / 256, 256>>>(out, part, S, boff, cnt);
        } else {
            dim3 gs(8, (cnt + 127) / 128);
            k_bk<<<gs, 128>>>(out, Wb + (size_t)k * NS * NS, S, aoff, boff, cnt);
        }
    }
    // result in `out`
}

// round 10
// speedup vs baseline: 3.6238x; 1.0755x over previous
#include <cuda_runtime.h>

#define NS   512
#define TN   20000
#define ND   2000
#define DTC  30.0f
#define RAD  8          // fill radix (anchors every 8 rows)
#define NANCH 2500      // TN / RAD
#define SKROWS 1280     // split-K partial rows (max anchor-level cnt = 1250)

// ---------------- static scratch (no allocations allowed) ----------------
__device__ float d_Lt[NS * NS];            // (dt*A)^T
__device__ float d_G1[NS * NS];
__device__ float d_G2[NS * NS];
// T slots: 1..8 = (M^q)^T ; 9=T16, 10=T32, 11=T64, 12=T128 ; slot 0 unused
__device__ float d_T[13][NS * NS];
__device__ float d_vec[8 * NS];            // temps g,h,Lg,L2g,L3g,Lh,L2h,L3h
__device__ float d_vw[RAD * 5 * NS];       // vw[j][i][c] = (M^j [w1..w4,v])[c], j=0..7
__device__ float d_cv[RAD * NS];           // cv[p-1] = sum_{j<p} M^j v, p=1..8
__device__ float d_part[4 * SKROWS * NS];  // split-K partials

// ---------------- small helpers ----------------
__global__ void k_tpose(const float* __restrict__ A, float* __restrict__ Lt) {
    int idx = blockIdx.x * blockDim.x + threadIdx.x;
    if (idx < NS * NS) {
        int i = idx >> 9, j = idx & 511;
        Lt[idx] = DTC * A[j * NS + i];
    }
}

__global__ void k_gh(const float* __restrict__ B, const float* __restrict__ Q,
                     float* __restrict__ g, float* __restrict__ h) {
    int i = blockIdx.x * blockDim.x + threadIdx.x;
    if (i < NS) {
        g[i] = B[i * 9];
        float s = 0.f;
#pragma unroll
        for (int m = 0; m < 8; m++) s += B[i * 9 + 1 + m] * Q[m];
        h[i] = s;
    }
}

__global__ void k_matvec2(const float* __restrict__ A,
                          const float* __restrict__ x1, const float* __restrict__ x2,
                          float* __restrict__ y1, float* __restrict__ y2, float scale) {
    __shared__ float red1[128], red2[128];
    int row = blockIdx.x;
    float s1 = 0.f, s2 = 0.f;
    for (int j = threadIdx.x; j < NS; j += 128) {
        float a = A[row * NS + j];
        s1 += a * x1[j];
        s2 += a * x2[j];
    }
    red1[threadIdx.x] = s1; red2[threadIdx.x] = s2;
    __syncthreads();
    for (int st = 64; st > 0; st >>= 1) {
        if (threadIdx.x < st) {
            red1[threadIdx.x] += red1[threadIdx.x + st];
            red2[threadIdx.x] += red2[threadIdx.x + st];
        }
        __syncthreads();
    }
    if (threadIdx.x == 0) { y1[row] = scale * red1[0]; y2[row] = scale * red2[0]; }
}

// writes w1..w4, v into vw[0][0..4]
__global__ void k_combine(const float* __restrict__ vec, float* __restrict__ vw) {
    int i = blockIdx.x * blockDim.x + threadIdx.x;
    if (i >= NS) return;
    const float G   = vec[0 * NS + i], H   = vec[1 * NS + i];
    const float LG  = vec[2 * NS + i], L2G = vec[3 * NS + i], L3G = vec[4 * NS + i];
    const float LH  = vec[5 * NS + i], L2H = vec[6 * NS + i], L3H = vec[7 * NS + i];
    const float c = DTC / 8.0f;
    vw[0 * NS + i] = c * (G + LG + (L2G + L3G) * (1.0f / 3.0f));
    vw[1 * NS + i] = c * (3.0f * G + 2.0f * LG + L2G);
    vw[2 * NS + i] = c * (3.0f * G + LG);
    vw[3 * NS + i] = c * G;
    vw[4 * NS + i] = DTC * (H + 0.5f * LH + L2H * (1.0f / 6.0f) + L3H * (1.0f / 24.0f));
}

__global__ void k_axpyI(const float* __restrict__ X, float* __restrict__ C, float alpha) {
    int idx = blockIdx.x * blockDim.x + threadIdx.x;
    if (idx < NS * NS) {
        int i = idx >> 9, j = idx & 511;
        C[idx] = alpha * X[idx] + (i == j ? 1.0f : 0.0f);
    }
}

// ---------------- 512^3 GEMM: C = alpha*(A@B) + (addI ? I : 0) ----------------
__global__ void __launch_bounds__(128) k_gemm512(
    const float* __restrict__ A, const float* __restrict__ B, float* __restrict__ C,
    float alpha, int addI)
{
    __shared__ float As[16][36];
    __shared__ float Bs[16][68];
    const int t  = threadIdx.x;
    const int tx = t & 7, ty = t >> 3;
    const int r0 = blockIdx.y * 32, c0 = blockIdx.x * 64;

    const int ar = t >> 2, ac4 = (t & 3) * 4;
    const int br = t >> 4, bc4 = (t & 15) * 4;

    unsigned long long acc[2][4];
#pragma unroll
    for (int m = 0; m < 2; m++)
#pragma unroll
        for (int p = 0; p < 4; p++) acc[m][p] = 0ull;

    float4 av = *(const float4*)(A + (size_t)(r0 + ar) * NS + ac4);
    float4 b0 = *(const float4*)(B + (size_t)br * NS + c0 + bc4);
    float4 b1 = *(const float4*)(B + (size_t)(br + 8) * NS + c0 + bc4);

    for (int it = 0; it < 32; ++it) {
        As[ac4 + 0][ar] = av.x; As[ac4 + 1][ar] = av.y;
        As[ac4 + 2][ar] = av.z; As[ac4 + 3][ar] = av.w;
        *(float4*)&Bs[br][bc4]     = b0;
        *(float4*)&Bs[br + 8][bc4] = b1;
        __syncthreads();
        if (it < 31) {
            const int k0 = (it + 1) * 16;
            av = *(const float4*)(A + (size_t)(r0 + ar) * NS + k0 + ac4);
            b0 = *(const float4*)(B + (size_t)(k0 + br) * NS + c0 + bc4);
            b1 = *(const float4*)(B + (size_t)(k0 + br + 8) * NS + c0 + bc4);
        }
#pragma unroll
        for (int kk = 0; kk < 16; ++kk) {
            float a0 = As[kk][ty * 2 + 0];
            float a1 = As[kk][ty * 2 + 1];
            ulonglong2 bp0 = *(const ulonglong2*)&Bs[kk][tx * 8];
            ulonglong2 bp1 = *(const ulonglong2*)&Bs[kk][tx * 8 + 4];
            unsigned long long bv[4] = {bp0.x, bp0.y, bp1.x, bp1.y};
            unsigned long long av0, av1;
            asm("mov.b64 %0, {%1, %1};" : "=l"(av0) : "f"(a0));
            asm("mov.b64 %0, {%1, %1};" : "=l"(av1) : "f"(a1));
#pragma unroll
            for (int p = 0; p < 4; p++) {
                asm("fma.rn.f32x2 %0, %1, %2, %0;" : "+l"(acc[0][p]) : "l"(av0), "l"(bv[p]));
                asm("fma.rn.f32x2 %0, %1, %2, %0;" : "+l"(acc[1][p]) : "l"(av1), "l"(bv[p]));
            }
        }
        __syncthreads();
    }
#pragma unroll
    for (int m = 0; m < 2; m++) {
        const int row = r0 + ty * 2 + m;
#pragma unroll
        for (int p = 0; p < 4; p++) {
            float lo, hi;
            asm("mov.b64 {%0, %1}, %2;" : "=f"(lo), "=f"(hi) : "l"(acc[m][p]));
            int col = c0 + tx * 8 + 2 * p;
            C[(size_t)row * NS + col]     = alpha * lo + ((addI && row == col)     ? 1.0f : 0.0f);
            C[(size_t)row * NS + col + 1] = alpha * hi + ((addI && row == col + 1) ? 1.0f : 0.0f);
        }
    }
}

// batched variant over T slots: C_z = A_z @ B_z, slot indices a0+z*da etc.
__global__ void __launch_bounds__(128) k_gemm512z(
    float* __restrict__ Tb, int a0, int da, int b0, int db, int c0i, int dc)
{
    const int z = blockIdx.z;
    const float* A = Tb + (size_t)(a0 + z * da) * NS * NS;
    const float* B = Tb + (size_t)(b0 + z * db) * NS * NS;
    float*       C = Tb + (size_t)(c0i + z * dc) * NS * NS;

    __shared__ float As[16][36];
    __shared__ float Bs[16][68];
    const int t  = threadIdx.x;
    const int tx = t & 7, ty = t >> 3;
    const int r0 = blockIdx.y * 32, c0 = blockIdx.x * 64;

    const int ar = t >> 2, ac4 = (t & 3) * 4;
    const int br = t >> 4, bc4 = (t & 15) * 4;

    unsigned long long acc[2][4];
#pragma unroll
    for (int m = 0; m < 2; m++)
#pragma unroll
        for (int p = 0; p < 4; p++) acc[m][p] = 0ull;

    float4 av = *(const float4*)(A + (size_t)(r0 + ar) * NS + ac4);
    float4 b0v = *(const float4*)(B + (size_t)br * NS + c0 + bc4);
    float4 b1v = *(const float4*)(B + (size_t)(br + 8) * NS + c0 + bc4);

    for (int it = 0; it < 32; ++it) {
        As[ac4 + 0][ar] = av.x; As[ac4 + 1][ar] = av.y;
        As[ac4 + 2][ar] = av.z; As[ac4 + 3][ar] = av.w;
        *(float4*)&Bs[br][bc4]     = b0v;
        *(float4*)&Bs[br + 8][bc4] = b1v;
        __syncthreads();
        if (it < 31) {
            const int k0 = (it + 1) * 16;
            av  = *(const float4*)(A + (size_t)(r0 + ar) * NS + k0 + ac4);
            b0v = *(const float4*)(B + (size_t)(k0 + br) * NS + c0 + bc4);
            b1v = *(const float4*)(B + (size_t)(k0 + br + 8) * NS + c0 + bc4);
        }
#pragma unroll
        for (int kk = 0; kk < 16; ++kk) {
            float a0f = As[kk][ty * 2 + 0];
            float a1f = As[kk][ty * 2 + 1];
            ulonglong2 bp0 = *(const ulonglong2*)&Bs[kk][tx * 8];
            ulonglong2 bp1 = *(const ulonglong2*)&Bs[kk][tx * 8 + 4];
            unsigned long long bv[4] = {bp0.x, bp0.y, bp1.x, bp1.y};
            unsigned long long av0, av1;
            asm("mov.b64 %0, {%1, %1};" : "=l"(av0) : "f"(a0f));
            asm("mov.b64 %0, {%1, %1};" : "=l"(av1) : "f"(a1f));
#pragma unroll
            for (int p = 0; p < 4; p++) {
                asm("fma.rn.f32x2 %0, %1, %2, %0;" : "+l"(acc[0][p]) : "l"(av0), "l"(bv[p]));
                asm("fma.rn.f32x2 %0, %1, %2, %0;" : "+l"(acc[1][p]) : "l"(av1), "l"(bv[p]));
            }
        }
        __syncthreads();
    }
#pragma unroll
    for (int m = 0; m < 2; m++) {
        const int row = r0 + ty * 2 + m;
#pragma unroll
        for (int p = 0; p < 4; p++) {
            float lo, hi;
            asm("mov.b64 {%0, %1}, %2;" : "=f"(lo), "=f"(hi) : "l"(acc[m][p]));
            int col = c0 + tx * 8 + 2 * p;
            C[(size_t)row * NS + col]     = lo;
            C[(size_t)row * NS + col + 1] = hi;
        }
    }
}

// ---------------- vw[j] = [w1..w4,v] @ T_j  (j=1..7, batched) ----------------
__global__ void k_vw(const float* __restrict__ Tb, float* __restrict__ vw) {
    const int j = blockIdx.z + 1;
    const float* T = Tb + (size_t)j * NS * NS;
    const int c = blockIdx.x * 256 + threadIdx.x;

    __shared__ float v0s[5 * NS];
    for (int i = threadIdx.x; i < 5 * NS; i += 256) v0s[i] = vw[i];  // j=0 block
    __syncthreads();

    float acc0 = 0.f, acc1 = 0.f, acc2 = 0.f, acc3 = 0.f, acc4 = 0.f;
    for (int k = 0; k < NS; ++k) {
        float tk = T[(size_t)k * NS + c];
        acc0 += v0s[0 * NS + k] * tk;
        acc1 += v0s[1 * NS + k] * tk;
        acc2 += v0s[2 * NS + k] * tk;
        acc3 += v0s[3 * NS + k] * tk;
        acc4 += v0s[4 * NS + k] * tk;
    }
    float* o = vw + (size_t)j * 5 * NS;
    o[0 * NS + c] = acc0; o[1 * NS + c] = acc1; o[2 * NS + c] = acc2;
    o[3 * NS + c] = acc3; o[4 * NS + c] = acc4;
}

// cv[p-1] = sum_{j<p} vw[j][4]
__global__ void k_cv(const float* __restrict__ vw, float* __restrict__ cv) {
    int c = blockIdx.x * 256 + threadIdx.x;
    if (c >= NS) return;
    float acc = 0.f;
    for (int j = 0; j < RAD; ++j) {
        acc += vw[((size_t)j * 5 + 4) * NS + c];
        cv[(size_t)j * NS + c] = acc;
    }
}

// ---------------- E0: every row gets its within-group-of-8 forcing prefix ----------------
__device__ __forceinline__ float dev_interp(const float* __restrict__ Tt,
                                            const float* __restrict__ Tv, float tq) {
    if (tq <= Tt[0])      return Tv[0];
    if (tq >= Tt[ND - 1]) return Tv[ND - 1];
    int lo = 0, hi = ND - 1;
    while (hi - lo > 1) {
        int mid = (lo + hi) >> 1;
        if (Tt[mid] <= tq) lo = mid; else hi = mid;
    }
    float x0 = Tt[lo], x1 = Tt[lo + 1];
    return Tv[lo] + (tq - x0) * (Tv[lo + 1] - Tv[lo]) / (x1 - x0);
}

__global__ void k_buildE0(const float* __restrict__ Tt, const float* __restrict__ Tv,
                          const float* __restrict__ iv, const float* __restrict__ vw,
                          const float* __restrict__ cv, float* __restrict__ E0)
{
    const int n = blockIdx.x;
    const int t = threadIdx.x;  // 128
    if (n == 0) {
        for (int i = t; i < NS; i += 128) E0[i] = iv[i];
        return;
    }
    const int q = n & (RAD - 1);
    const int p = (q == 0) ? RAD : q;     // number of d-terms in prefix

    __shared__ float s[RAD][4];
    if (t < 4 * p) {
        int jj = t >> 2, ii = t & 3;
        float tq = (float)(n - 1 - jj) * DTC + (float)ii * 10.0f;
        s[jj][ii] = dev_interp(Tt, Tv, tq);
    }
    __syncthreads();

    float* row = E0 + (size_t)n * NS;
    const float* cvp = cv + (size_t)(p - 1) * NS;
    for (int i = t; i < NS; i += 128) {
        float acc = cvp[i];
        for (int jj = 0; jj < p; ++jj) {
            const float* base = vw + (size_t)jj * 5 * NS;
            acc += s[jj][0] * base[i]          + s[jj][1] * base[NS + i]
                 + s[jj][2] * base[2 * NS + i] + s[jj][3] * base[3 * NS + i];
        }
        row[i] = acc;
    }
}

// ---------------- split-K (x4) BK edge: partials for V[r*S+boff] += V[r*S+aoff]@W ----------------
__global__ void __launch_bounds__(128, 4) k_bk_sk(
    const float* __restrict__ V, const float* __restrict__ W,
    float* __restrict__ part, int S, int aoff, int cnt)
{
    __shared__ float As[16][132];
    __shared__ float Bs[16][68];

    const int t  = threadIdx.x;
    const int tx = t & 7;
    const int ty = t >> 3;
    const int r0 = blockIdx.y * 128;
    const int c0 = blockIdx.x * 64;
    const int z  = blockIdx.z;
    const int kb = z * 128;

    const int  ar  = t >> 2;
    const int  ac4 = (t & 3) * 4;
    long gr[4]; bool v[4];
#pragma unroll
    for (int g = 0; g < 4; g++) {
        int lo = r0 + ar + 32 * g;
        v[g]  = lo < cnt;
        gr[g] = (long)lo * S + aoff;
    }

    const int br  = t >> 4;
    const int bc4 = (t & 15) * 4;

    unsigned long long acc[8][4];
#pragma unroll
    for (int m = 0; m < 8; m++)
#pragma unroll
        for (int p = 0; p < 4; p++) acc[m][p] = 0ull;

    const float4 f4z = make_float4(0.f, 0.f, 0.f, 0.f);
    float4 av[4], b0, b1;
#pragma unroll
    for (int g = 0; g < 4; g++)
        av[g] = v[g] ? *(const float4*)(V + gr[g] * NS + kb + ac4) : f4z;
    b0 = *(const float4*)(W + (size_t)(kb + br) * NS + c0 + bc4);
    b1 = *(const float4*)(W + (size_t)(kb + br + 8) * NS + c0 + bc4);

    for (int it = 0; it < 8; ++it) {
#pragma unroll
        for (int g = 0; g < 4; g++) {
            As[ac4 + 0][ar + 32 * g] = av[g].x;
            As[ac4 + 1][ar + 32 * g] = av[g].y;
            As[ac4 + 2][ar + 32 * g] = av[g].z;
            As[ac4 + 3][ar + 32 * g] = av[g].w;
        }
        *(float4*)&Bs[br][bc4]     = b0;
        *(float4*)&Bs[br + 8][bc4] = b1;
        __syncthreads();

        if (it < 7) {
            const int k0 = kb + (it + 1) * 16;
#pragma unroll
            for (int g = 0; g < 4; g++)
                av[g] = v[g] ? *(const float4*)(V + gr[g] * NS + k0 + ac4) : f4z;
            b0 = *(const float4*)(W + (size_t)(k0 + br) * NS + c0 + bc4);
            b1 = *(const float4*)(W + (size_t)(k0 + br + 8) * NS + c0 + bc4);
        }

#pragma unroll
        for (int kk = 0; kk < 16; ++kk) {
            float a[8];
            *(float4*)&a[0] = *(const float4*)&As[kk][ty * 8];
            *(float4*)&a[4] = *(const float4*)&As[kk][ty * 8 + 4];
            ulonglong2 bp0 = *(const ulonglong2*)&Bs[kk][tx * 8];
            ulonglong2 bp1 = *(const ulonglong2*)&Bs[kk][tx * 8 + 4];
            unsigned long long bv[4] = {bp0.x, bp0.y, bp1.x, bp1.y};
#pragma unroll
            for (int m = 0; m < 8; m++) {
                unsigned long long avv;
                asm("mov.b64 %0, {%1, %1};" : "=l"(avv) : "f"(a[m]));
#pragma unroll
                for (int p = 0; p < 4; p++)
                    asm("fma.rn.f32x2 %0, %1, %2, %0;"
                        : "+l"(acc[m][p]) : "l"(avv), "l"(bv[p]));
            }
        }
        __syncthreads();
    }

#pragma unroll
    for (int m = 0; m < 8; m++) {
        const int r = r0 + ty * 8 + m;
        if (r < cnt) {
            float c[8];
#pragma unroll
            for (int p = 0; p < 4; p++)
                asm("mov.b64 {%0, %1}, %2;"
                    : "=f"(c[2 * p]), "=f"(c[2 * p + 1]) : "l"(acc[m][p]));
            float* prow = part + ((size_t)z * SKROWS + r) * NS + c0 + tx * 8;
            *(float4*)prow       = make_float4(c[0], c[1], c[2], c[3]);
            *(float4*)(prow + 4) = make_float4(c[4], c[5], c[6], c[7]);
        }
    }
}

// deterministic reduce of the 4 partials into dest rows
__global__ void k_bk_red(float* __restrict__ V, const float* __restrict__ part,
                         int S, int boff, int cnt)
{
    int idx = blockIdx.x * 256 + threadIdx.x;
    int total = cnt * (NS / 4);
    if (idx >= total) return;
    int r  = idx / (NS / 4);
    int c4 = (idx - r * (NS / 4)) * 4;
    float4 p0 = *(const float4*)(part + ((size_t)0 * SKROWS + r) * NS + c4);
    float4 p1 = *(const float4*)(part + ((size_t)1 * SKROWS + r) * NS + c4);
    float4 p2 = *(const float4*)(part + ((size_t)2 * SKROWS + r) * NS + c4);
    float4 p3 = *(const float4*)(part + ((size_t)3 * SKROWS + r) * NS + c4);
    float* dst = V + ((size_t)r * S + boff) * NS + c4;
    float4 d = *(const float4*)dst;
    d.x += (p0.x + p1.x) + (p2.x + p3.x);
    d.y += (p0.y + p1.y) + (p2.y + p3.y);
    d.z += (p0.z + p1.z) + (p2.z + p3.z);
    d.w += (p0.w + p1.w) + (p2.w + p3.w);
    *(float4*)dst = d;
}

// ---------------- flat fill: x[8r+q] = E[8r+q] + (M^q) x[8r], q=1..7, one launch ----------------
__global__ void __launch_bounds__(128, 4) k_fillz(
    float* __restrict__ V, const float* __restrict__ Tb, int cnt)
{
    const int q = blockIdx.z + 1;
    const float* W = Tb + (size_t)q * NS * NS;

    __shared__ float As[16][132];
    __shared__ float Bs[16][68];

    const int t  = threadIdx.x;
    const int tx = t & 7;
    const int ty = t >> 3;
    const int r0 = blockIdx.y * 128;
    const int c0 = blockIdx.x * 64;

    const int  ar  = t >> 2;
    const int  ac4 = (t & 3) * 4;
    long gr[4]; bool v[4];
#pragma unroll
    for (int g = 0; g < 4; g++) {
        int lo = r0 + ar + 32 * g;
        v[g]  = lo < cnt;
        gr[g] = (long)lo * RAD;
    }

    const int br  = t >> 4;
    const int bc4 = (t & 15) * 4;

    unsigned long long acc[8][4];
#pragma unroll
    for (int m = 0; m < 8; m++)
#pragma unroll
        for (int p = 0; p < 4; p++) acc[m][p] = 0ull;

    const float4 f4z = make_float4(0.f, 0.f, 0.f, 0.f);
    float4 av[4], b0, b1;
#pragma unroll
    for (int g = 0; g < 4; g++)
        av[g] = v[g] ? *(const float4*)(V + gr[g] * NS + ac4) : f4z;
    b0 = *(const float4*)(W + (size_t)br * NS + c0 + bc4);
    b1 = *(const float4*)(W + (size_t)(br + 8) * NS + c0 + bc4);

    for (int it = 0; it < 32; ++it) {
#pragma unroll
        for (int g = 0; g < 4; g++) {
            As[ac4 + 0][ar + 32 * g] = av[g].x;
            As[ac4 + 1][ar + 32 * g] = av[g].y;
            As[ac4 + 2][ar + 32 * g] = av[g].z;
            As[ac4 + 3][ar + 32 * g] = av[g].w;
        }
        *(float4*)&Bs[br][bc4]     = b0;
        *(float4*)&Bs[br + 8][bc4] = b1;
        __syncthreads();

        if (it < 31) {
            const int k0 = (it + 1) * 16;
#pragma unroll
            for (int g = 0; g < 4; g++)
                av[g] = v[g] ? *(const float4*)(V + gr[g] * NS + k0 + ac4) : f4z;
            b0 = *(const float4*)(W + (size_t)(k0 + br) * NS + c0 + bc4);
            b1 = *(const float4*)(W + (size_t)(k0 + br + 8) * NS + c0 + bc4);
        }

#pragma unroll
        for (int kk = 0; kk < 16; ++kk) {
            float a[8];
            *(float4*)&a[0] = *(const float4*)&As[kk][ty * 8];
            *(float4*)&a[4] = *(const float4*)&As[kk][ty * 8 + 4];
            ulonglong2 bp0 = *(const ulonglong2*)&Bs[kk][tx * 8];
            ulonglong2 bp1 = *(const ulonglong2*)&Bs[kk][tx * 8 + 4];
            unsigned long long bv[4] = {bp0.x, bp0.y, bp1.x, bp1.y};
#pragma unroll
            for (int m = 0; m < 8; m++) {
                unsigned long long avv;
                asm("mov.b64 %0, {%1, %1};" : "=l"(avv) : "f"(a[m]));
#pragma unroll
                for (int p = 0; p < 4; p++)
                    asm("fma.rn.f32x2 %0, %1, %2, %0;"
                        : "+l"(acc[m][p]) : "l"(avv), "l"(bv[p]));
            }
        }
        __syncthreads();
    }

#pragma unroll
    for (int m = 0; m < 8; m++) {
        const int r = r0 + ty * 8 + m;
        if (r < cnt) {
            const long dr = (long)r * RAD + q;
            float* erow = V + dr * NS + c0 + tx * 8;
            float4 e0 = *(const float4*)erow;
            float4 e1 = *(const float4*)(erow + 4);
            float c[8];
#pragma unroll
            for (int p = 0; p < 4; p++)
                asm("mov.b64 {%0, %1}, %2;"
                    : "=f"(c[2 * p]), "=f"(c[2 * p + 1]) : "l"(acc[m][p]));
            float4 o0 = make_float4(c[0] + e0.x, c[1] + e0.y, c[2] + e0.z, c[3] + e0.w);
            float4 o1 = make_float4(c[4] + e1.x, c[5] + e1.y, c[6] + e1.z, c[7] + e1.w);
            *(float4*)erow       = o0;
            *(float4*)(erow + 4) = o1;
        }
    }
}

// ---------------- host orchestration (graph-capturable, alloc-free) ----------------
extern "C" void kernel_launch(void* const* d_in, const int* in_sizes, int n_in,
                              void* d_out, int out_size) {
    const float* A  = (const float*)d_in[0];
    const float* Bm = (const float*)d_in[1];
    const float* Q  = (const float*)d_in[2];
    const float* Tt = (const float*)d_in[3];
    const float* Tv = (const float*)d_in[4];
    const float* iv = (const float*)d_in[5];
    float* out = (float*)d_out;

    float *Lt, *G1, *G2, *Tb, *vec, *vw, *cv, *part;
    cudaGetSymbolAddress((void**)&Lt,   d_Lt);
    cudaGetSymbolAddress((void**)&G1,   d_G1);
    cudaGetSymbolAddress((void**)&G2,   d_G2);
    cudaGetSymbolAddress((void**)&Tb,   d_T);
    cudaGetSymbolAddress((void**)&vec,  d_vec);
    cudaGetSymbolAddress((void**)&vw,   d_vw);
    cudaGetSymbolAddress((void**)&cv,   d_cv);
    cudaGetSymbolAddress((void**)&part, d_part);

    const size_t NS2 = (size_t)NS * NS;

    // Lt = (dt*A)^T
    k_tpose<<<1024, 256>>>(A, Lt);

    // forcing vectors w1..w4, v  (into vw[0])
    k_gh<<<2, 256>>>(Bm, Q, vec + 0 * NS, vec + 1 * NS);
    k_matvec2<<<512, 128>>>(A, vec + 0 * NS, vec + 1 * NS, vec + 2 * NS, vec + 5 * NS, DTC);
    k_matvec2<<<512, 128>>>(A, vec + 2 * NS, vec + 5 * NS, vec + 3 * NS, vec + 6 * NS, DTC);
    k_matvec2<<<512, 128>>>(A, vec + 3 * NS, vec + 6 * NS, vec + 4 * NS, vec + 7 * NS, DTC);
    k_combine<<<2, 256>>>(vec, vw);

    // T1 = M^T via Horner
    dim3 gg(8, 16);
    k_axpyI<<<1024, 256>>>(Lt, G1, 0.25f);
    k_gemm512<<<gg, 128>>>(Lt, G1, G2, 1.0f / 3.0f, 1);
    k_gemm512<<<gg, 128>>>(Lt, G2, G1, 0.5f, 1);
    k_gemm512<<<gg, 128>>>(Lt, G1, Tb + 1 * NS2, 1.0f, 1);

    // power chain (powers of M commute; any operand order valid)
    k_gemm512z<<<dim3(8, 16, 1), 128>>>(Tb, 1, 0, 1, 0, 2, 0);   // T2
    k_gemm512z<<<dim3(8, 16, 2), 128>>>(Tb, 1, 1, 2, 0, 3, 1);   // T3=T1@T2, T4=T2@T2
    k_gemm512z<<<dim3(8, 16, 4), 128>>>(Tb, 1, 1, 4, 0, 5, 1);   // T5..T8 = T{1..4}@T4
    k_gemm512z<<<dim3(8, 16, 1), 128>>>(Tb, 8, 0, 8, 0, 9, 0);   // T16
    k_gemm512z<<<dim3(8, 16, 1), 128>>>(Tb, 9, 0, 9, 0, 10, 0);  // T32
    k_gemm512z<<<dim3(8, 16, 1), 128>>>(Tb, 10, 0, 10, 0, 11, 0); // T64
    k_gemm512z<<<dim3(8, 16, 1), 128>>>(Tb, 11, 0, 11, 0, 12, 0); // T128

    // vw[j] = [w,v] @ T_j (j=1..7) ; cv cumsums
    k_vw<<<dim3(2, 1, 7), 256>>>(Tb, vw);
    k_cv<<<2, 256>>>(vw, cv);

    // E0: within-group-of-8 prefixes everywhere
    k_buildE0<<<TN, 128>>>(Tt, Tv, iv, vw, cv, out);

    // ---- anchor Brent-Kung over 2500 anchors (rows = 8*o), levels j=0..4
    const int Wsel[5] = {8, 9, 10, 11, 12};  // T8, T16, T32, T64, T128
    // up-sweep
    for (int j = 0; j < 5; ++j) {
        const int Sa = 1 << (j + 1);
        const int cnt = NANCH >> (j + 1);
        const int Sm = RAD * Sa;
        const int aoff = RAD * ((1 << j) - 1);
        const int boff = RAD * (Sa - 1);
        dim3 gs(8, (cnt + 127) / 128, 4);
        k_bk_sk<<<gs, 128>>>(out, Tb + (size_t)Wsel[j] * NS2, part, Sm, aoff, cnt);
        k_bk_red<<<(cnt * (NS / 4) + 255) / 256, 256>>>(out, part, Sm, boff, cnt);
    }
    // down-sweep
    for (int j = 4; j >= 0; --j) {
        const int Sa = 1 << (j + 1);
        const int boffa = Sa - 1 + (1 << j);
        const int cnt = (NANCH - 1 - boffa) / Sa + 1;
        const int Sm = RAD * Sa;
        const int aoff = RAD * (Sa - 1);
        const int boff = RAD * boffa;
        dim3 gs(8, (cnt + 127) / 128, 4);
        k_bk_sk<<<gs, 128>>>(out, Tb + (size_t)Wsel[j] * NS2, part, Sm, aoff, cnt);
        k_bk_red<<<(cnt * (NS / 4) + 255) / 256, 256>>>(out, part, Sm, boff, cnt);
    }

    // ---- flat fill: all non-anchor rows in one launch
    dim3 gf(8, (NANCH + 127) / 128, RAD - 1);
    k_fillz<<<gf, 128>>>(out, Tb, NANCH);
    // result in `out`
}